// round 6
// baseline (speedup 1.0000x reference)
#include <cuda_runtime.h>
#include <cuda_bf16.h>
#include <math.h>

typedef unsigned int u32;

// Problem constants
#define BATCH 2
#define SEQ   2048
#define DMODEL 1024
#define NHEAD 16
#define HD    64
#define MTOT  (BATCH*SEQ)
#define NQT   (SEQ/128)     // 16 q-tiles of 128

// ---------------- scratch ----------------
__device__ float g_q[BATCH*SEQ*DMODEL];
__device__ float g_k[BATCH*SEQ*DMODEL];
__device__ float g_v[BATCH*SEQ*DMODEL];
__device__ float g_attn[BATCH*SEQ*DMODEL];
__device__ float g_xr[BATCH*SEQ*DMODEL];      // tf32-rounded x
__device__ float g_wr[4*DMODEL*DMODEL];       // tf32-rounded wq,wk,wv,wo

// ---------------- helpers ----------------
__device__ __forceinline__ u32 f2tf(float x) {
    u32 u;
    asm("cvt.rna.tf32.f32 %0, %1;" : "=r"(u) : "f"(x));
    return u;
}
__device__ __forceinline__ float tfbits(float x) {
    return __uint_as_float(f2tf(x));
}
__device__ __forceinline__ void mma_tf32(float* d, const u32* a, const u32* b) {
    asm volatile(
        "mma.sync.aligned.m16n8k8.row.col.f32.tf32.tf32.f32 "
        "{%0,%1,%2,%3},{%4,%5,%6,%7},{%8,%9},{%0,%1,%2,%3};"
        : "+f"(d[0]), "+f"(d[1]), "+f"(d[2]), "+f"(d[3])
        : "r"(a[0]), "r"(a[1]), "r"(a[2]), "r"(a[3]), "r"(b[0]), "r"(b[1]));
}
__device__ __forceinline__ u32 ldsu(const float* p) {
    return __float_as_uint(*p);
}
__device__ __forceinline__ void cpa16(u32 smem_dst, const void* gptr) {
    asm volatile("cp.async.cg.shared.global [%0], [%1], 16;" :: "r"(smem_dst), "l"(gptr));
}
#define CP_COMMIT()  asm volatile("cp.async.commit_group;")
#define CP_WAIT1()   asm volatile("cp.async.wait_group 1;")
#define CP_WAIT0()   asm volatile("cp.async.wait_group 0;")

// ---------------- prepass: tf32-round an array (float4 grid-stride) ----------------
__global__ void round_tf32_kernel(const float* __restrict__ src,
                                  float* __restrict__ dst, int n4)
{
    int i = blockIdx.x * blockDim.x + threadIdx.x;
    if (i < n4) {
        float4 v = ((const float4*)src)[i];
        float4 o;
        o.x = tfbits(v.x); o.y = tfbits(v.y);
        o.z = tfbits(v.z); o.w = tfbits(v.w);
        ((float4*)dst)[i] = o;
    }
}

// ---------------- GEMM: C[M,N] = A[M,K] @ W[N,K]^T + bias[N] ----------------
// Inputs pre-rounded to tf32. 128x128x32 block, cp.async 2-stage pipeline.
#define GBM 128
#define GBN 128
#define GBK 32
#define GASTR 36                 // row stride (floats); 36%32==4 -> conflict-free frags
#define GSTAGE (GBM*GASTR)       // 4608 floats per stage per matrix

__global__ __launch_bounds__(256, 2) void gemm_nt_bias(
    const float* __restrict__ A, const float* __restrict__ W,
    const float* __restrict__ bias, float* __restrict__ C,
    int M, int N, int K)
{
    extern __shared__ float gsm[];
    float* As = gsm;                // 2 stages
    float* Ws = gsm + 2 * GSTAGE;

    const int tid  = threadIdx.x;
    const int warp = tid >> 5;
    const int lane = tid & 31;
    const int g    = lane >> 2;
    const int t4   = lane & 3;
    const int wm   = warp >> 2;   // 0..1
    const int wn   = warp & 3;    // 0..3
    const int m0   = blockIdx.y * GBM;
    const int n0   = blockIdx.x * GBN;

    const u32 asb = (u32)__cvta_generic_to_shared(As);
    const u32 wsb = (u32)__cvta_generic_to_shared(Ws);

    float acc[4][4][4];
#pragma unroll
    for (int i = 0; i < 4; i++)
#pragma unroll
        for (int j = 0; j < 4; j++)
#pragma unroll
            for (int r = 0; r < 4; r++) acc[i][j][r] = 0.f;

    // copy geometry: 1024 16B-chunks per matrix per stage, 4 per thread
    const int crow = tid >> 1;                  // rows 0..127 (2 threads/row)
    const int ck0  = (tid & 1) * 16;            // first chunk col (floats)

    // issue stage for k-block kb into buffer buf
    auto issue = [&](int buf, int kb) {
        const int kbase = kb * GBK;
#pragma unroll
        for (int l = 0; l < 2; l++) {
            int row = crow;
            int kc  = ck0 + l * 4;              // 0,4 / 16,20
            cpa16(asb + (u32)((buf * GSTAGE + row * GASTR + kc) * 4),
                  &A[(size_t)(m0 + row) * K + kbase + kc]);
            cpa16(wsb + (u32)((buf * GSTAGE + row * GASTR + kc) * 4),
                  &W[(size_t)(n0 + row) * K + kbase + kc]);
        }
#pragma unroll
        for (int l = 0; l < 2; l++) {
            int row = crow;
            int kc  = ck0 + 8 + l * 4;          // 8,12 / 24,28
            cpa16(asb + (u32)((buf * GSTAGE + row * GASTR + kc) * 4),
                  &A[(size_t)(m0 + row) * K + kbase + kc]);
            cpa16(wsb + (u32)((buf * GSTAGE + row * GASTR + kc) * 4),
                  &W[(size_t)(n0 + row) * K + kbase + kc]);
        }
        CP_COMMIT();
    };

    const int NKB = K / GBK;   // 32
    issue(0, 0);

    for (int kb = 0; kb < NKB; kb++) {
        const int buf = kb & 1;
        if (kb + 1 < NKB) {
            issue(buf ^ 1, kb + 1);
            CP_WAIT1();
        } else {
            CP_WAIT0();
        }
        __syncthreads();

        const float* Ab = As + buf * GSTAGE;
        const float* Wb = Ws + buf * GSTAGE;

#pragma unroll
        for (int ks = 0; ks < 4; ks++) {
            const int k = ks * 8;
            u32 af[4][4], bf[4][2];
#pragma unroll
            for (int i = 0; i < 4; i++) {
                int rb = wm * 64 + i * 16 + g;
                af[i][0] = ldsu(&Ab[(rb)     * GASTR + k + t4]);
                af[i][1] = ldsu(&Ab[(rb + 8) * GASTR + k + t4]);
                af[i][2] = ldsu(&Ab[(rb)     * GASTR + k + t4 + 4]);
                af[i][3] = ldsu(&Ab[(rb + 8) * GASTR + k + t4 + 4]);
            }
#pragma unroll
            for (int j = 0; j < 4; j++) {
                int nb = wn * 32 + j * 8 + g;
                bf[j][0] = ldsu(&Wb[nb * GASTR + k + t4]);
                bf[j][1] = ldsu(&Wb[nb * GASTR + k + t4 + 4]);
            }
#pragma unroll
            for (int i = 0; i < 4; i++)
#pragma unroll
                for (int j = 0; j < 4; j++)
                    mma_tf32(acc[i][j], af[i], bf[j]);
        }
        __syncthreads();
    }

    // epilogue: bias + store
#pragma unroll
    for (int j = 0; j < 4; j++) {
        int col = n0 + wn * 32 + j * 8 + 2 * t4;
        float b0 = bias[col], b1 = bias[col + 1];
#pragma unroll
        for (int i = 0; i < 4; i++) {
            int r0 = m0 + wm * 64 + i * 16 + g;
            float2 o0 = { acc[i][j][0] + b0, acc[i][j][1] + b1 };
            float2 o1 = { acc[i][j][2] + b0, acc[i][j][3] + b1 };
            *(float2*)&C[(size_t)r0 * N + col]       = o0;
            *(float2*)&C[(size_t)(r0 + 8) * N + col] = o1;
        }
    }
}

// ---------------- Flash attention (causal), tf32 mma, paired q-tiles ----------------
#define AQT 128
#define AKT 64
#define KSTR 68
#define VSTR 72
#define PSTR 68

#define SM_K  0
#define SM_V  (AKT * KSTR)
#define SM_Q  (SM_V + AKT * VSTR)
#define SM_P  (SM_Q + AQT * PSTR)
#define SM_FL (SM_P + AQT * PSTR)     // 26368 floats = 105472 B

__global__ __launch_bounds__(256, 2) void attn_kernel(
    const float* __restrict__ Q, const float* __restrict__ Kb,
    const float* __restrict__ Vb, float* __restrict__ O)
{
    extern __shared__ float sm[];
    float* Ks = sm + SM_K;
    float* Vs = sm + SM_V;
    float* Qs = sm + SM_Q;
    float* Ps = sm + SM_P;

    const int tid  = threadIdx.x;
    const int warp = tid >> 5;
    const int lane = tid & 31;
    const int g    = lane >> 2;
    const int t4   = lane & 3;

    const int h = blockIdx.y;
    const int b = blockIdx.z;
    const size_t base = ((size_t)b * SEQ) * DMODEL + (size_t)h * HD;
    const float scale = 0.125f;
    const int w16 = warp * 16;

    // Each block handles two complementary q-tiles: total work is constant (34 K-tiles).
    for (int half = 0; half < 2; half++) {
        const int qtile = half ? (int)blockIdx.x : (NQT - 1 - (int)blockIdx.x);
        const int q0 = qtile * AQT;

        __syncthreads();   // protect Qs from previous half's readers

        // Load Q tile (128 x 64), pre-scaled, tf32-rounded
#pragma unroll
        for (int l = 0; l < 8; l++) {
            int f4  = tid + l * 256;
            int row = f4 >> 4;
            int col = (f4 & 15) * 4;
            float4 v = *(const float4*)&Q[base + (size_t)(q0 + row) * DMODEL + col];
            float4 o;
            o.x = tfbits(v.x * scale); o.y = tfbits(v.y * scale);
            o.z = tfbits(v.z * scale); o.w = tfbits(v.w * scale);
            *(float4*)&Qs[row * PSTR + col] = o;
        }

        float of[8][4];
#pragma unroll
        for (int j = 0; j < 8; j++)
#pragma unroll
            for (int r = 0; r < 4; r++) of[j][r] = 0.f;
        float m0r = -1e30f, m1r = -1e30f, l0r = 0.f, l1r = 0.f;

        const int ntiles = 2 * qtile + 2;

        for (int jt = 0; jt < ntiles; jt++) {
            __syncthreads();
            // Load K and V tiles (64 x 64 each)
#pragma unroll
            for (int l = 0; l < 4; l++) {
                int f4  = tid + l * 256;
                int row = f4 >> 4;
                int col = (f4 & 15) * 4;
                size_t gaddr = base + (size_t)(jt * AKT + row) * DMODEL + col;
                float4 kv = *(const float4*)&Kb[gaddr];
                float4 ko;
                ko.x = tfbits(kv.x); ko.y = tfbits(kv.y);
                ko.z = tfbits(kv.z); ko.w = tfbits(kv.w);
                *(float4*)&Ks[row * KSTR + col] = ko;
                float4 vv = *(const float4*)&Vb[gaddr];
                float4 vo;
                vo.x = tfbits(vv.x); vo.y = tfbits(vv.y);
                vo.z = tfbits(vv.z); vo.w = tfbits(vv.w);
                *(float4*)&Vs[row * VSTR + col] = vo;
            }
            __syncthreads();

            // ---- S = Q @ K^T ----
            float s[8][4];
#pragma unroll
            for (int j = 0; j < 8; j++)
#pragma unroll
                for (int r = 0; r < 4; r++) s[j][r] = 0.f;

#pragma unroll
            for (int ks = 0; ks < 8; ks++) {
                const int k = ks * 8;
                u32 a[4];
                a[0] = ldsu(&Qs[(w16 + g)     * PSTR + k + t4]);
                a[1] = ldsu(&Qs[(w16 + g + 8) * PSTR + k + t4]);
                a[2] = ldsu(&Qs[(w16 + g)     * PSTR + k + t4 + 4]);
                a[3] = ldsu(&Qs[(w16 + g + 8) * PSTR + k + t4 + 4]);
#pragma unroll
                for (int j = 0; j < 8; j++) {
                    u32 bfr[2];
                    bfr[0] = ldsu(&Ks[(j * 8 + g) * KSTR + k + t4]);
                    bfr[1] = ldsu(&Ks[(j * 8 + g) * KSTR + k + t4 + 4]);
                    mma_tf32(s[j], a, bfr);
                }
            }

            // ---- causal mask (diagonal tiles only) ----
            if (jt >= 2 * qtile) {
                int r0 = q0 + w16 + g, r1 = r0 + 8;
#pragma unroll
                for (int j = 0; j < 8; j++) {
                    int c = jt * AKT + j * 8 + 2 * t4;
                    if (c     > r0) s[j][0] = -1e30f;
                    if (c + 1 > r0) s[j][1] = -1e30f;
                    if (c     > r1) s[j][2] = -1e30f;
                    if (c + 1 > r1) s[j][3] = -1e30f;
                }
            }

            // ---- online softmax ----
            float mt0 = -1e30f, mt1 = -1e30f;
#pragma unroll
            for (int j = 0; j < 8; j++) {
                mt0 = fmaxf(mt0, fmaxf(s[j][0], s[j][1]));
                mt1 = fmaxf(mt1, fmaxf(s[j][2], s[j][3]));
            }
            mt0 = fmaxf(mt0, __shfl_xor_sync(0xffffffffu, mt0, 1));
            mt0 = fmaxf(mt0, __shfl_xor_sync(0xffffffffu, mt0, 2));
            mt1 = fmaxf(mt1, __shfl_xor_sync(0xffffffffu, mt1, 1));
            mt1 = fmaxf(mt1, __shfl_xor_sync(0xffffffffu, mt1, 2));

            float mn0 = fmaxf(m0r, mt0), mn1 = fmaxf(m1r, mt1);
            float corr0 = __expf(m0r - mn0), corr1 = __expf(m1r - mn1);
            m0r = mn0; m1r = mn1;

            float ps0 = 0.f, ps1 = 0.f;
#pragma unroll
            for (int j = 0; j < 8; j++) {
                s[j][0] = __expf(s[j][0] - mn0); ps0 += s[j][0];
                s[j][1] = __expf(s[j][1] - mn0); ps0 += s[j][1];
                s[j][2] = __expf(s[j][2] - mn1); ps1 += s[j][2];
                s[j][3] = __expf(s[j][3] - mn1); ps1 += s[j][3];
            }
            ps0 += __shfl_xor_sync(0xffffffffu, ps0, 1);
            ps0 += __shfl_xor_sync(0xffffffffu, ps0, 2);
            ps1 += __shfl_xor_sync(0xffffffffu, ps1, 1);
            ps1 += __shfl_xor_sync(0xffffffffu, ps1, 2);
            l0r = l0r * corr0 + ps0;
            l1r = l1r * corr1 + ps1;

#pragma unroll
            for (int j = 0; j < 8; j++) {
                of[j][0] *= corr0; of[j][1] *= corr0;
                of[j][2] *= corr1; of[j][3] *= corr1;
            }

            // store P (tf32) to warp-private smem rows
#pragma unroll
            for (int j = 0; j < 8; j++) {
                int rr = w16 + g, col = j * 8 + 2 * t4;
                Ps[rr * PSTR + col]           = tfbits(s[j][0]);
                Ps[rr * PSTR + col + 1]       = tfbits(s[j][1]);
                Ps[(rr + 8) * PSTR + col]     = tfbits(s[j][2]);
                Ps[(rr + 8) * PSTR + col + 1] = tfbits(s[j][3]);
            }
            __syncwarp();

            // ---- O += P @ V ----
#pragma unroll
            for (int ks = 0; ks < 8; ks++) {
                const int k = ks * 8;
                u32 pa[4];
                pa[0] = ldsu(&Ps[(w16 + g)     * PSTR + k + t4]);
                pa[1] = ldsu(&Ps[(w16 + g + 8) * PSTR + k + t4]);
                pa[2] = ldsu(&Ps[(w16 + g)     * PSTR + k + t4 + 4]);
                pa[3] = ldsu(&Ps[(w16 + g + 8) * PSTR + k + t4 + 4]);
#pragma unroll
                for (int j = 0; j < 8; j++) {
                    u32 bfr[2];
                    bfr[0] = ldsu(&Vs[(k + t4)     * VSTR + j * 8 + g]);
                    bfr[1] = ldsu(&Vs[(k + t4 + 4) * VSTR + j * 8 + g]);
                    mma_tf32(of[j], pa, bfr);
                }
            }
            __syncwarp();
        }

        // ---- epilogue (tf32-rounded so the O-projection can consume raw bits) ----
        float inv0 = 1.f / l0r, inv1 = 1.f / l1r;
        int r0 = q0 + w16 + g, r1 = r0 + 8;
#pragma unroll
        for (int j = 0; j < 8; j++) {
            int col = j * 8 + 2 * t4;
            float2 o0 = { tfbits(of[j][0] * inv0), tfbits(of[j][1] * inv0) };
            float2 o1 = { tfbits(of[j][2] * inv1), tfbits(of[j][3] * inv1) };
            *(float2*)&O[base + (size_t)r0 * DMODEL + col] = o0;
            *(float2*)&O[base + (size_t)r1 * DMODEL + col] = o1;
        }
    }
}

// ---------------- launch ----------------
extern "C" void kernel_launch(void* const* d_in, const int* in_sizes, int n_in,
                              void* d_out, int out_size)
{
    const float* x  = (const float*)d_in[0];
    const float* wq = (const float*)d_in[1];
    const float* bq = (const float*)d_in[2];
    const float* wk = (const float*)d_in[3];
    const float* bk = (const float*)d_in[4];
    const float* wv = (const float*)d_in[5];
    const float* bv = (const float*)d_in[6];
    const float* wo = (const float*)d_in[7];
    const float* bo = (const float*)d_in[8];
    float* out = (float*)d_out;

    float *qb, *kb, *vb, *ab, *xr, *wr;
    cudaGetSymbolAddress((void**)&qb, g_q);
    cudaGetSymbolAddress((void**)&kb, g_k);
    cudaGetSymbolAddress((void**)&vb, g_v);
    cudaGetSymbolAddress((void**)&ab, g_attn);
    cudaGetSymbolAddress((void**)&xr, g_xr);
    cudaGetSymbolAddress((void**)&wr, g_wr);

    float* wqr = wr;
    float* wkr = wr + DMODEL*DMODEL;
    float* wvr = wr + 2*DMODEL*DMODEL;
    float* wor = wr + 3*DMODEL*DMODEL;

    // prepass: tf32-round x + weights
    {
        int n4x = MTOT * DMODEL / 4;
        int n4w = DMODEL * DMODEL / 4;
        round_tf32_kernel<<<(n4x + 255) / 256, 256>>>(x,  xr,  n4x);
        round_tf32_kernel<<<(n4w + 255) / 256, 256>>>(wq, wqr, n4w);
        round_tf32_kernel<<<(n4w + 255) / 256, 256>>>(wk, wkr, n4w);
        round_tf32_kernel<<<(n4w + 255) / 256, 256>>>(wv, wvr, n4w);
        round_tf32_kernel<<<(n4w + 255) / 256, 256>>>(wo, wor, n4w);
    }

    const int smem_gemm = 4 * GSTAGE * (int)sizeof(float);   // 73728 B
    cudaFuncSetAttribute(gemm_nt_bias, cudaFuncAttributeMaxDynamicSharedMemorySize, smem_gemm);

    dim3 gdim(DMODEL / GBN, MTOT / GBM);   // (8, 32)
    gemm_nt_bias<<<gdim, 256, smem_gemm>>>(xr, wqr, bq, qb, MTOT, DMODEL, DMODEL);
    gemm_nt_bias<<<gdim, 256, smem_gemm>>>(xr, wkr, bk, kb, MTOT, DMODEL, DMODEL);
    gemm_nt_bias<<<gdim, 256, smem_gemm>>>(xr, wvr, bv, vb, MTOT, DMODEL, DMODEL);

    const int smem_attn = SM_FL * (int)sizeof(float);   // 105472 B
    cudaFuncSetAttribute(attn_kernel, cudaFuncAttributeMaxDynamicSharedMemorySize, smem_attn);
    attn_kernel<<<dim3(NQT / 2, NHEAD, BATCH), 256, smem_attn>>>(qb, kb, vb, ab);

    gemm_nt_bias<<<gdim, 256, smem_gemm>>>(ab, wor, bo, out, MTOT, DMODEL, DMODEL);
}

// round 7
// speedup vs baseline: 1.1841x; 1.1841x over previous
#include <cuda_runtime.h>
#include <cuda_bf16.h>
#include <math.h>

typedef unsigned int u32;   // avoid any <cstdint> dependency

// Problem constants
#define BATCH 2
#define SEQ   2048
#define DMODEL 1024
#define NHEAD 16
#define HD    64
#define MTOT  (BATCH*SEQ)
#define NQT   (SEQ/128)     // 16 q-tiles of 128

// ---------------- scratch ----------------
__device__ float g_q[BATCH*SEQ*DMODEL];
__device__ float g_k[BATCH*SEQ*DMODEL];
__device__ float g_v[BATCH*SEQ*DMODEL];
__device__ float g_attn[BATCH*SEQ*DMODEL];

// ---------------- helpers ----------------
__device__ __forceinline__ u32 f2tf(float x) {
    u32 u;
    asm("cvt.rna.tf32.f32 %0, %1;" : "=r"(u) : "f"(x));
    return u;
}
__device__ __forceinline__ float tfbits(float x) {  // tf32-round, keep as float bits
    return __uint_as_float(f2tf(x));
}
__device__ __forceinline__ void mma_tf32(float* d, const u32* a, const u32* b) {
    asm volatile(
        "mma.sync.aligned.m16n8k8.row.col.f32.tf32.tf32.f32 "
        "{%0,%1,%2,%3},{%4,%5,%6,%7},{%8,%9},{%0,%1,%2,%3};"
        : "+f"(d[0]), "+f"(d[1]), "+f"(d[2]), "+f"(d[3])
        : "r"(a[0]), "r"(a[1]), "r"(a[2]), "r"(a[3]), "r"(b[0]), "r"(b[1]));
}
__device__ __forceinline__ u32 ldsu(const float* p) {
    return __float_as_uint(*p);
}

// ---------------- GEMM: C[M,N] = A[M,K] @ W[N,K]^T + bias[N] (tf32 mma) ----------------
// Block 128x128, BK=32. 8 warps in 2(M) x 4(N); warp tile 64x32.  (round-5 version)
#define GBM 128
#define GBN 128
#define GBK 32
#define GASTR 36   // 36 mod 32 == 4 -> conflict-free fragment LDS

__global__ __launch_bounds__(256, 2) void gemm_nt_bias(
    const float* __restrict__ A, const float* __restrict__ W,
    const float* __restrict__ bias, float* __restrict__ C,
    int M, int N, int K)
{
    __shared__ float As[GBM * GASTR];
    __shared__ float Ws[GBM * GASTR];

    const int tid  = threadIdx.x;
    const int warp = tid >> 5;
    const int lane = tid & 31;
    const int g    = lane >> 2;   // group id 0..7
    const int t4   = lane & 3;    // thread-in-group 0..3
    const int wm   = warp >> 2;   // 0..1
    const int wn   = warp & 3;    // 0..3
    const int m0   = blockIdx.y * GBM;
    const int n0   = blockIdx.x * GBN;

    float acc[4][4][4];
#pragma unroll
    for (int i = 0; i < 4; i++)
#pragma unroll
        for (int j = 0; j < 4; j++)
#pragma unroll
            for (int r = 0; r < 4; r++) acc[i][j][r] = 0.f;

    // register stage for global prefetch: 4 float4 per tile per thread
    float4 ar[4], wr4[4];
    const int srow[4] = { (tid + 0)   >> 3, (tid + 256) >> 3,
                          (tid + 512) >> 3, (tid + 768) >> 3 };
    const int skq = (tid & 7) * 4;

    // prologue load k0 = 0
#pragma unroll
    for (int l = 0; l < 4; l++) {
        ar[l]  = *(const float4*)&A[(size_t)(m0 + srow[l]) * K + skq];
        wr4[l] = *(const float4*)&W[(size_t)(n0 + srow[l]) * K + skq];
    }

    const int NKB = K / GBK;
    for (int kb = 0; kb < NKB; kb++) {
        // store stage to smem with tf32 rounding
#pragma unroll
        for (int l = 0; l < 4; l++) {
            float4 a4, w4;
            a4.x = tfbits(ar[l].x); a4.y = tfbits(ar[l].y);
            a4.z = tfbits(ar[l].z); a4.w = tfbits(ar[l].w);
            w4.x = tfbits(wr4[l].x); w4.y = tfbits(wr4[l].y);
            w4.z = tfbits(wr4[l].z); w4.w = tfbits(wr4[l].w);
            *(float4*)&As[srow[l] * GASTR + skq] = a4;
            *(float4*)&Ws[srow[l] * GASTR + skq] = w4;
        }
        __syncthreads();

        // prefetch next tile
        if (kb + 1 < NKB) {
            int k0 = (kb + 1) * GBK;
#pragma unroll
            for (int l = 0; l < 4; l++) {
                ar[l]  = *(const float4*)&A[(size_t)(m0 + srow[l]) * K + k0 + skq];
                wr4[l] = *(const float4*)&W[(size_t)(n0 + srow[l]) * K + k0 + skq];
            }
        }

        // compute 4 k-steps of 8
#pragma unroll
        for (int ks = 0; ks < 4; ks++) {
            const int k = ks * 8;
            u32 af[4][4], bf[4][2];
#pragma unroll
            for (int i = 0; i < 4; i++) {
                int rb = wm * 64 + i * 16 + g;
                af[i][0] = ldsu(&As[(rb)     * GASTR + k + t4]);
                af[i][1] = ldsu(&As[(rb + 8) * GASTR + k + t4]);
                af[i][2] = ldsu(&As[(rb)     * GASTR + k + t4 + 4]);
                af[i][3] = ldsu(&As[(rb + 8) * GASTR + k + t4 + 4]);
            }
#pragma unroll
            for (int j = 0; j < 4; j++) {
                int nb = wn * 32 + j * 8 + g;
                bf[j][0] = ldsu(&Ws[nb * GASTR + k + t4]);
                bf[j][1] = ldsu(&Ws[nb * GASTR + k + t4 + 4]);
            }
#pragma unroll
            for (int i = 0; i < 4; i++)
#pragma unroll
                for (int j = 0; j < 4; j++)
                    mma_tf32(acc[i][j], af[i], bf[j]);
        }
        __syncthreads();
    }

    // epilogue: bias + store
#pragma unroll
    for (int j = 0; j < 4; j++) {
        int col = n0 + wn * 32 + j * 8 + 2 * t4;
        float b0 = bias[col], b1 = bias[col + 1];
#pragma unroll
        for (int i = 0; i < 4; i++) {
            int r0 = m0 + wm * 64 + i * 16 + g;
            float2 o0 = { acc[i][j][0] + b0, acc[i][j][1] + b1 };
            float2 o1 = { acc[i][j][2] + b0, acc[i][j][3] + b1 };
            *(float2*)&C[(size_t)r0 * N + col]       = o0;
            *(float2*)&C[(size_t)(r0 + 8) * N + col] = o1;
        }
    }
}

// ---------------- Flash attention (causal), tf32 mma, paired q-tiles ----------------
#define AQT 128
#define AKT 64
#define KSTR 68
#define VSTR 72
#define PSTR 68

#define SM_K  0
#define SM_V  (AKT * KSTR)
#define SM_Q  (SM_V + AKT * VSTR)
#define SM_P  (SM_Q + AQT * PSTR)
#define SM_FL (SM_P + AQT * PSTR)     // 26368 floats = 105472 B

__global__ __launch_bounds__(256, 2) void attn_kernel(
    const float* __restrict__ Q, const float* __restrict__ Kb,
    const float* __restrict__ Vb, float* __restrict__ O)
{
    extern __shared__ float sm[];
    float* Ks = sm + SM_K;
    float* Vs = sm + SM_V;
    float* Qs = sm + SM_Q;
    float* Ps = sm + SM_P;

    const int tid  = threadIdx.x;
    const int warp = tid >> 5;
    const int lane = tid & 31;
    const int g    = lane >> 2;
    const int t4   = lane & 3;

    const int h = blockIdx.y;
    const int b = blockIdx.z;
    const size_t base = ((size_t)b * SEQ) * DMODEL + (size_t)h * HD;
    const float scale = 0.125f;
    const int w16 = warp * 16;

    // Each block handles two complementary q-tiles: uniform 34 K-tiles total.
    for (int half = 0; half < 2; half++) {
        const int qtile = half ? (int)blockIdx.x : (NQT - 1 - (int)blockIdx.x);
        const int q0 = qtile * AQT;

        __syncthreads();   // protect Qs from previous half's readers

        // Load Q tile (128 x 64), pre-scaled, tf32-rounded
#pragma unroll
        for (int l = 0; l < 8; l++) {
            int f4  = tid + l * 256;
            int row = f4 >> 4;
            int col = (f4 & 15) * 4;
            float4 v = *(const float4*)&Q[base + (size_t)(q0 + row) * DMODEL + col];
            float4 o;
            o.x = tfbits(v.x * scale); o.y = tfbits(v.y * scale);
            o.z = tfbits(v.z * scale); o.w = tfbits(v.w * scale);
            *(float4*)&Qs[row * PSTR + col] = o;
        }

        float of[8][4];
#pragma unroll
        for (int j = 0; j < 8; j++)
#pragma unroll
            for (int r = 0; r < 4; r++) of[j][r] = 0.f;
        float m0r = -1e30f, m1r = -1e30f, l0r = 0.f, l1r = 0.f;

        const int ntiles = 2 * qtile + 2;

        for (int jt = 0; jt < ntiles; jt++) {
            __syncthreads();
            // Load K and V tiles (64 x 64 each)
#pragma unroll
            for (int l = 0; l < 4; l++) {
                int f4  = tid + l * 256;
                int row = f4 >> 4;
                int col = (f4 & 15) * 4;
                size_t gaddr = base + (size_t)(jt * AKT + row) * DMODEL + col;
                float4 kv = *(const float4*)&Kb[gaddr];
                float4 ko;
                ko.x = tfbits(kv.x); ko.y = tfbits(kv.y);
                ko.z = tfbits(kv.z); ko.w = tfbits(kv.w);
                *(float4*)&Ks[row * KSTR + col] = ko;
                float4 vv = *(const float4*)&Vb[gaddr];
                float4 vo;
                vo.x = tfbits(vv.x); vo.y = tfbits(vv.y);
                vo.z = tfbits(vv.z); vo.w = tfbits(vv.w);
                *(float4*)&Vs[row * VSTR + col] = vo;
            }
            __syncthreads();

            // ---- S = Q @ K^T ----
            float s[8][4];
#pragma unroll
            for (int j = 0; j < 8; j++)
#pragma unroll
                for (int r = 0; r < 4; r++) s[j][r] = 0.f;

#pragma unroll
            for (int ks = 0; ks < 8; ks++) {
                const int k = ks * 8;
                u32 a[4];
                a[0] = ldsu(&Qs[(w16 + g)     * PSTR + k + t4]);
                a[1] = ldsu(&Qs[(w16 + g + 8) * PSTR + k + t4]);
                a[2] = ldsu(&Qs[(w16 + g)     * PSTR + k + t4 + 4]);
                a[3] = ldsu(&Qs[(w16 + g + 8) * PSTR + k + t4 + 4]);
#pragma unroll
                for (int j = 0; j < 8; j++) {
                    u32 bfr[2];
                    bfr[0] = ldsu(&Ks[(j * 8 + g) * KSTR + k + t4]);
                    bfr[1] = ldsu(&Ks[(j * 8 + g) * KSTR + k + t4 + 4]);
                    mma_tf32(s[j], a, bfr);
                }
            }

            // ---- causal mask (diagonal tiles only) ----
            if (jt >= 2 * qtile) {
                int r0 = q0 + w16 + g, r1 = r0 + 8;
#pragma unroll
                for (int j = 0; j < 8; j++) {
                    int c = jt * AKT + j * 8 + 2 * t4;
                    if (c     > r0) s[j][0] = -1e30f;
                    if (c + 1 > r0) s[j][1] = -1e30f;
                    if (c     > r1) s[j][2] = -1e30f;
                    if (c + 1 > r1) s[j][3] = -1e30f;
                }
            }

            // ---- online softmax ----
            float mt0 = -1e30f, mt1 = -1e30f;
#pragma unroll
            for (int j = 0; j < 8; j++) {
                mt0 = fmaxf(mt0, fmaxf(s[j][0], s[j][1]));
                mt1 = fmaxf(mt1, fmaxf(s[j][2], s[j][3]));
            }
            mt0 = fmaxf(mt0, __shfl_xor_sync(0xffffffffu, mt0, 1));
            mt0 = fmaxf(mt0, __shfl_xor_sync(0xffffffffu, mt0, 2));
            mt1 = fmaxf(mt1, __shfl_xor_sync(0xffffffffu, mt1, 1));
            mt1 = fmaxf(mt1, __shfl_xor_sync(0xffffffffu, mt1, 2));

            float mn0 = fmaxf(m0r, mt0), mn1 = fmaxf(m1r, mt1);
            float corr0 = __expf(m0r - mn0), corr1 = __expf(m1r - mn1);
            m0r = mn0; m1r = mn1;

            float ps0 = 0.f, ps1 = 0.f;
#pragma unroll
            for (int j = 0; j < 8; j++) {
                s[j][0] = __expf(s[j][0] - mn0); ps0 += s[j][0];
                s[j][1] = __expf(s[j][1] - mn0); ps0 += s[j][1];
                s[j][2] = __expf(s[j][2] - mn1); ps1 += s[j][2];
                s[j][3] = __expf(s[j][3] - mn1); ps1 += s[j][3];
            }
            ps0 += __shfl_xor_sync(0xffffffffu, ps0, 1);
            ps0 += __shfl_xor_sync(0xffffffffu, ps0, 2);
            ps1 += __shfl_xor_sync(0xffffffffu, ps1, 1);
            ps1 += __shfl_xor_sync(0xffffffffu, ps1, 2);
            l0r = l0r * corr0 + ps0;
            l1r = l1r * corr1 + ps1;

#pragma unroll
            for (int j = 0; j < 8; j++) {
                of[j][0] *= corr0; of[j][1] *= corr0;
                of[j][2] *= corr1; of[j][3] *= corr1;
            }

            // store P (tf32) to warp-private smem rows
#pragma unroll
            for (int j = 0; j < 8; j++) {
                int rr = w16 + g, col = j * 8 + 2 * t4;
                Ps[rr * PSTR + col]           = tfbits(s[j][0]);
                Ps[rr * PSTR + col + 1]       = tfbits(s[j][1]);
                Ps[(rr + 8) * PSTR + col]     = tfbits(s[j][2]);
                Ps[(rr + 8) * PSTR + col + 1] = tfbits(s[j][3]);
            }
            __syncwarp();

            // ---- O += P @ V ----
#pragma unroll
            for (int ks = 0; ks < 8; ks++) {
                const int k = ks * 8;
                u32 pa[4];
                pa[0] = ldsu(&Ps[(w16 + g)     * PSTR + k + t4]);
                pa[1] = ldsu(&Ps[(w16 + g + 8) * PSTR + k + t4]);
                pa[2] = ldsu(&Ps[(w16 + g)     * PSTR + k + t4 + 4]);
                pa[3] = ldsu(&Ps[(w16 + g + 8) * PSTR + k + t4 + 4]);
#pragma unroll
                for (int j = 0; j < 8; j++) {
                    u32 bfr[2];
                    bfr[0] = ldsu(&Vs[(k + t4)     * VSTR + j * 8 + g]);
                    bfr[1] = ldsu(&Vs[(k + t4 + 4) * VSTR + j * 8 + g]);
                    mma_tf32(of[j], pa, bfr);
                }
            }
            __syncwarp();
        }

        // ---- epilogue ----
        float inv0 = 1.f / l0r, inv1 = 1.f / l1r;
        int r0 = q0 + w16 + g, r1 = r0 + 8;
#pragma unroll
        for (int j = 0; j < 8; j++) {
            int col = j * 8 + 2 * t4;
            float2 o0 = { of[j][0] * inv0, of[j][1] * inv0 };
            float2 o1 = { of[j][2] * inv1, of[j][3] * inv1 };
            *(float2*)&O[base + (size_t)r0 * DMODEL + col] = o0;
            *(float2*)&O[base + (size_t)r1 * DMODEL + col] = o1;
        }
    }
}

// ---------------- launch ----------------
extern "C" void kernel_launch(void* const* d_in, const int* in_sizes, int n_in,
                              void* d_out, int out_size)
{
    const float* x  = (const float*)d_in[0];
    const float* wq = (const float*)d_in[1];
    const float* bq = (const float*)d_in[2];
    const float* wk = (const float*)d_in[3];
    const float* bk = (const float*)d_in[4];
    const float* wv = (const float*)d_in[5];
    const float* bv = (const float*)d_in[6];
    const float* wo = (const float*)d_in[7];
    const float* bo = (const float*)d_in[8];
    float* out = (float*)d_out;

    float *qb, *kb, *vb, *ab;
    cudaGetSymbolAddress((void**)&qb, g_q);
    cudaGetSymbolAddress((void**)&kb, g_k);
    cudaGetSymbolAddress((void**)&vb, g_v);
    cudaGetSymbolAddress((void**)&ab, g_attn);

    dim3 gdim(DMODEL / GBN, MTOT / GBM);   // (8, 32)
    gemm_nt_bias<<<gdim, 256>>>(x, wq, bq, qb, MTOT, DMODEL, DMODEL);
    gemm_nt_bias<<<gdim, 256>>>(x, wk, bk, kb, MTOT, DMODEL, DMODEL);
    gemm_nt_bias<<<gdim, 256>>>(x, wv, bv, vb, MTOT, DMODEL, DMODEL);

    const int smem_attn = SM_FL * (int)sizeof(float);   // 105472 B
    cudaFuncSetAttribute(attn_kernel, cudaFuncAttributeMaxDynamicSharedMemorySize, smem_attn);
    attn_kernel<<<dim3(NQT / 2, NHEAD, BATCH), 256, smem_attn>>>(qb, kb, vb, ab);

    gemm_nt_bias<<<gdim, 256>>>(ab, wo, bo, out, MTOT, DMODEL, DMODEL);
}

// round 8
// speedup vs baseline: 1.2086x; 1.0207x over previous
#include <cuda_runtime.h>
#include <cuda_bf16.h>
#include <math.h>

typedef unsigned int u32;

// Problem constants
#define BATCH 2
#define SEQ   2048
#define DMODEL 1024
#define NHEAD 16
#define HD    64
#define MTOT  (BATCH*SEQ)
#define NQT   (SEQ/128)

// ---------------- scratch ----------------
__device__ float g_q[BATCH*SEQ*DMODEL];
__device__ float g_k[BATCH*SEQ*DMODEL];
__device__ float g_v[BATCH*SEQ*DMODEL];
__device__ float g_attn[BATCH*SEQ*DMODEL];

// ---------------- helpers ----------------
__device__ __forceinline__ u32 f2tf(float x) {
    u32 u;
    asm("cvt.rna.tf32.f32 %0, %1;" : "=r"(u) : "f"(x));
    return u;
}
__device__ __forceinline__ float tfbits(float x) {
    return __uint_as_float(f2tf(x));
}
__device__ __forceinline__ void mma_tf32(float* d, const u32* a, const u32* b) {
    asm volatile(
        "mma.sync.aligned.m16n8k8.row.col.f32.tf32.tf32.f32 "
        "{%0,%1,%2,%3},{%4,%5,%6,%7},{%8,%9},{%0,%1,%2,%3};"
        : "+f"(d[0]), "+f"(d[1]), "+f"(d[2]), "+f"(d[3])
        : "r"(a[0]), "r"(a[1]), "r"(a[2]), "r"(a[3]), "r"(b[0]), "r"(b[1]));
}
__device__ __forceinline__ u32 ldsu(const float* p) {
    return __float_as_uint(*p);
}

// ---------------- GEMM (unchanged round-5/7 version) ----------------
#define GBM 128
#define GBN 128
#define GBK 32
#define GASTR 36

__global__ __launch_bounds__(256, 2) void gemm_nt_bias(
    const float* __restrict__ A, const float* __restrict__ W,
    const float* __restrict__ bias, float* __restrict__ C,
    int M, int N, int K)
{
    __shared__ float As[GBM * GASTR];
    __shared__ float Ws[GBM * GASTR];

    const int tid  = threadIdx.x;
    const int warp = tid >> 5;
    const int lane = tid & 31;
    const int g    = lane >> 2;
    const int t4   = lane & 3;
    const int wm   = warp >> 2;
    const int wn   = warp & 3;
    const int m0   = blockIdx.y * GBM;
    const int n0   = blockIdx.x * GBN;

    float acc[4][4][4];
#pragma unroll
    for (int i = 0; i < 4; i++)
#pragma unroll
        for (int j = 0; j < 4; j++)
#pragma unroll
            for (int r = 0; r < 4; r++) acc[i][j][r] = 0.f;

    float4 ar[4], wr4[4];
    const int srow[4] = { (tid + 0)   >> 3, (tid + 256) >> 3,
                          (tid + 512) >> 3, (tid + 768) >> 3 };
    const int skq = (tid & 7) * 4;

#pragma unroll
    for (int l = 0; l < 4; l++) {
        ar[l]  = *(const float4*)&A[(size_t)(m0 + srow[l]) * K + skq];
        wr4[l] = *(const float4*)&W[(size_t)(n0 + srow[l]) * K + skq];
    }

    const int NKB = K / GBK;
    for (int kb = 0; kb < NKB; kb++) {
#pragma unroll
        for (int l = 0; l < 4; l++) {
            float4 a4, w4;
            a4.x = tfbits(ar[l].x); a4.y = tfbits(ar[l].y);
            a4.z = tfbits(ar[l].z); a4.w = tfbits(ar[l].w);
            w4.x = tfbits(wr4[l].x); w4.y = tfbits(wr4[l].y);
            w4.z = tfbits(wr4[l].z); w4.w = tfbits(wr4[l].w);
            *(float4*)&As[srow[l] * GASTR + skq] = a4;
            *(float4*)&Ws[srow[l] * GASTR + skq] = w4;
        }
        __syncthreads();

        if (kb + 1 < NKB) {
            int k0 = (kb + 1) * GBK;
#pragma unroll
            for (int l = 0; l < 4; l++) {
                ar[l]  = *(const float4*)&A[(size_t)(m0 + srow[l]) * K + k0 + skq];
                wr4[l] = *(const float4*)&W[(size_t)(n0 + srow[l]) * K + k0 + skq];
            }
        }

#pragma unroll
        for (int ks = 0; ks < 4; ks++) {
            const int k = ks * 8;
            u32 af[4][4], bf[4][2];
#pragma unroll
            for (int i = 0; i < 4; i++) {
                int rb = wm * 64 + i * 16 + g;
                af[i][0] = ldsu(&As[(rb)     * GASTR + k + t4]);
                af[i][1] = ldsu(&As[(rb + 8) * GASTR + k + t4]);
                af[i][2] = ldsu(&As[(rb)     * GASTR + k + t4 + 4]);
                af[i][3] = ldsu(&As[(rb + 8) * GASTR + k + t4 + 4]);
            }
#pragma unroll
            for (int j = 0; j < 4; j++) {
                int nb = wn * 32 + j * 8 + g;
                bf[j][0] = ldsu(&Ws[nb * GASTR + k + t4]);
                bf[j][1] = ldsu(&Ws[nb * GASTR + k + t4 + 4]);
            }
#pragma unroll
            for (int i = 0; i < 4; i++)
#pragma unroll
                for (int j = 0; j < 4; j++)
                    mma_tf32(acc[i][j], af[i], bf[j]);
        }
        __syncthreads();
    }

#pragma unroll
    for (int j = 0; j < 4; j++) {
        int col = n0 + wn * 32 + j * 8 + 2 * t4;
        float b0 = bias[col], b1 = bias[col + 1];
#pragma unroll
        for (int i = 0; i < 4; i++) {
            int r0 = m0 + wm * 64 + i * 16 + g;
            float2 o0 = { acc[i][j][0] + b0, acc[i][j][1] + b1 };
            float2 o1 = { acc[i][j][2] + b0, acc[i][j][3] + b1 };
            *(float2*)&C[(size_t)r0 * N + col]       = o0;
            *(float2*)&C[(size_t)(r0 + 8) * N + col] = o1;
        }
    }
}

// ---------------- Flash attention: fragment-packed smem + shuffle P ----------------
// Qp: 64 chunks (warp*8+ks) x 132 floats; fragment = LDS.128 at lane*4.
// Kp: 64 chunks (j*8+ks)    x 66 floats;  fragment = LDS.64  at lane*2.
// Vp: 64 chunks (ks*8+j)    x 66 floats;  fragment = LDS.64  at lane*2.
#define QP_CH 132
#define KP_CH 66
#define SM_QP 0
#define SM_KP (64 * QP_CH)                 // 8448
#define SM_VP (SM_KP + 64 * KP_CH)         // 12672
#define SM_FL (SM_VP + 64 * KP_CH)         // 16896 floats = 67584 B

__global__ __launch_bounds__(256, 2) void attn_kernel(
    const float* __restrict__ Q, const float* __restrict__ Kb,
    const float* __restrict__ Vb, float* __restrict__ O)
{
    extern __shared__ float sm[];
    float* Qp = sm + SM_QP;
    float* Kp = sm + SM_KP;
    float* Vp = sm + SM_VP;

    const int tid  = threadIdx.x;
    const int warp = tid >> 5;
    const int lane = tid & 31;
    const int g    = lane >> 2;
    const int t4   = lane & 3;

    const int h = blockIdx.y;
    const int b = blockIdx.z;
    const size_t base = ((size_t)b * SEQ) * DMODEL + (size_t)h * HD;
    const float scale = 0.125f;
    const int w16 = warp * 16;

    // shuffle sources for the C-frag -> A-frag permutation (within 4-lane group)
    const int srcA = (lane & ~3) | (t4 >> 1);
    const int srcB = srcA + 2;
    const bool odd = (t4 & 1) != 0;

    for (int half = 0; half < 2; half++) {
        const int qtile = half ? (int)blockIdx.x : (NQT - 1 - (int)blockIdx.x);
        const int q0 = qtile * 128;

        __syncthreads();   // previous half's readers of Qp done

        // ---- load Q tile (128x64) into packed fragment layout ----
#pragma unroll
        for (int l = 0; l < 8; l++) {
            int f4  = tid + l * 256;
            int row = f4 >> 4;
            int col = (f4 & 15) * 4;
            float4 v = *(const float4*)&Q[base + (size_t)(q0 + row) * DMODEL + col];
            int wb = row >> 4, r8 = (row >> 3) & 1, gg = row & 7;
            int ks = col >> 3, hf = (col >> 2) & 1;
            float* dst = &Qp[(wb * 8 + ks) * QP_CH + r8 + 2 * hf];
            dst[(gg * 4 + 0) * 4] = tfbits(v.x * scale);
            dst[(gg * 4 + 1) * 4] = tfbits(v.y * scale);
            dst[(gg * 4 + 2) * 4] = tfbits(v.z * scale);
            dst[(gg * 4 + 3) * 4] = tfbits(v.w * scale);
        }

        float of[8][4];
#pragma unroll
        for (int j = 0; j < 8; j++)
#pragma unroll
            for (int r = 0; r < 4; r++) of[j][r] = 0.f;
        float m0r = -1e30f, m1r = -1e30f, l0r = 0.f, l1r = 0.f;

        const int ntiles = 2 * qtile + 2;

        for (int jt = 0; jt < ntiles; jt++) {
            __syncthreads();
            // ---- load K,V tiles (64x64) into packed fragment layouts ----
#pragma unroll
            for (int l = 0; l < 4; l++) {
                int f4  = tid + l * 256;
                int row = f4 >> 4;
                int col = (f4 & 15) * 4;
                size_t gaddr = base + (size_t)(jt * 64 + row) * DMODEL + col;

                float4 kv = *(const float4*)&Kb[gaddr];
                {
                    int j = row >> 3, gg = row & 7;
                    int ks = col >> 3, hf = (col >> 2) & 1;
                    float* kd = &Kp[(j * 8 + ks) * KP_CH + hf];
                    kd[(gg * 4 + 0) * 2] = tfbits(kv.x);
                    kd[(gg * 4 + 1) * 2] = tfbits(kv.y);
                    kd[(gg * 4 + 2) * 2] = tfbits(kv.z);
                    kd[(gg * 4 + 3) * 2] = tfbits(kv.w);
                }
                float4 vv = *(const float4*)&Vb[gaddr];
                {
                    int ks = row >> 3, tt = row & 3, hf = (row >> 2) & 1;
                    int j = col >> 3, g0 = col & 7;
                    float* vd = &Vp[(ks * 8 + j) * KP_CH + hf];
                    vd[((g0 + 0) * 4 + tt) * 2] = tfbits(vv.x);
                    vd[((g0 + 1) * 4 + tt) * 2] = tfbits(vv.y);
                    vd[((g0 + 2) * 4 + tt) * 2] = tfbits(vv.z);
                    vd[((g0 + 3) * 4 + tt) * 2] = tfbits(vv.w);
                }
            }
            __syncthreads();

            // ---- S = Q @ K^T ----
            float s[8][4];
#pragma unroll
            for (int j = 0; j < 8; j++)
#pragma unroll
                for (int r = 0; r < 4; r++) s[j][r] = 0.f;

#pragma unroll
            for (int ks = 0; ks < 8; ks++) {
                float4 aq = *(const float4*)&Qp[(warp * 8 + ks) * QP_CH + lane * 4];
                u32 a[4] = { __float_as_uint(aq.x), __float_as_uint(aq.y),
                             __float_as_uint(aq.z), __float_as_uint(aq.w) };
#pragma unroll
                for (int j = 0; j < 8; j++) {
                    float2 kf = *(const float2*)&Kp[(j * 8 + ks) * KP_CH + lane * 2];
                    u32 bfr[2] = { __float_as_uint(kf.x), __float_as_uint(kf.y) };
                    mma_tf32(s[j], a, bfr);
                }
            }

            // ---- causal mask (diagonal tiles only) ----
            if (jt >= 2 * qtile) {
                int r0 = q0 + w16 + g, r1 = r0 + 8;
#pragma unroll
                for (int j = 0; j < 8; j++) {
                    int c = jt * 64 + j * 8 + 2 * t4;
                    if (c     > r0) s[j][0] = -1e30f;
                    if (c + 1 > r0) s[j][1] = -1e30f;
                    if (c     > r1) s[j][2] = -1e30f;
                    if (c + 1 > r1) s[j][3] = -1e30f;
                }
            }

            // ---- online softmax ----
            float mt0 = -1e30f, mt1 = -1e30f;
#pragma unroll
            for (int j = 0; j < 8; j++) {
                mt0 = fmaxf(mt0, fmaxf(s[j][0], s[j][1]));
                mt1 = fmaxf(mt1, fmaxf(s[j][2], s[j][3]));
            }
            mt0 = fmaxf(mt0, __shfl_xor_sync(0xffffffffu, mt0, 1));
            mt0 = fmaxf(mt0, __shfl_xor_sync(0xffffffffu, mt0, 2));
            mt1 = fmaxf(mt1, __shfl_xor_sync(0xffffffffu, mt1, 1));
            mt1 = fmaxf(mt1, __shfl_xor_sync(0xffffffffu, mt1, 2));

            float mn0 = fmaxf(m0r, mt0), mn1 = fmaxf(m1r, mt1);
            float corr0 = __expf(m0r - mn0), corr1 = __expf(m1r - mn1);
            m0r = mn0; m1r = mn1;

            float ps0 = 0.f, ps1 = 0.f;
#pragma unroll
            for (int j = 0; j < 8; j++) {
                s[j][0] = __expf(s[j][0] - mn0); ps0 += s[j][0];
                s[j][1] = __expf(s[j][1] - mn0); ps0 += s[j][1];
                s[j][2] = __expf(s[j][2] - mn1); ps1 += s[j][2];
                s[j][3] = __expf(s[j][3] - mn1); ps1 += s[j][3];
            }
            ps0 += __shfl_xor_sync(0xffffffffu, ps0, 1);
            ps0 += __shfl_xor_sync(0xffffffffu, ps0, 2);
            ps1 += __shfl_xor_sync(0xffffffffu, ps1, 1);
            ps1 += __shfl_xor_sync(0xffffffffu, ps1, 2);
            l0r = l0r * corr0 + ps0;
            l1r = l1r * corr1 + ps1;

#pragma unroll
            for (int j = 0; j < 8; j++) {
                of[j][0] *= corr0; of[j][1] *= corr0;
                of[j][2] *= corr1; of[j][3] *= corr1;
            }

            // tf32-round P in registers
#pragma unroll
            for (int j = 0; j < 8; j++) {
                s[j][0] = tfbits(s[j][0]); s[j][1] = tfbits(s[j][1]);
                s[j][2] = tfbits(s[j][2]); s[j][3] = tfbits(s[j][3]);
            }

            // ---- O += P @ V (P via intra-group shuffles) ----
#pragma unroll
            for (int ks = 0; ks < 8; ks++) {
                float v0 = __shfl_sync(0xffffffffu, s[ks][0], srcA);
                float v1 = __shfl_sync(0xffffffffu, s[ks][1], srcA);
                float v2 = __shfl_sync(0xffffffffu, s[ks][2], srcA);
                float v3 = __shfl_sync(0xffffffffu, s[ks][3], srcA);
                float w0 = __shfl_sync(0xffffffffu, s[ks][0], srcB);
                float w1 = __shfl_sync(0xffffffffu, s[ks][1], srcB);
                float w2 = __shfl_sync(0xffffffffu, s[ks][2], srcB);
                float w3 = __shfl_sync(0xffffffffu, s[ks][3], srcB);
                u32 pa[4];
                pa[0] = __float_as_uint(odd ? v1 : v0);
                pa[1] = __float_as_uint(odd ? v3 : v2);
                pa[2] = __float_as_uint(odd ? w1 : w0);
                pa[3] = __float_as_uint(odd ? w3 : w2);
#pragma unroll
                for (int j = 0; j < 8; j++) {
                    float2 vf = *(const float2*)&Vp[(ks * 8 + j) * KP_CH + lane * 2];
                    u32 bfr[2] = { __float_as_uint(vf.x), __float_as_uint(vf.y) };
                    mma_tf32(of[j], pa, bfr);
                }
            }
        }

        // ---- epilogue ----
        float inv0 = 1.f / l0r, inv1 = 1.f / l1r;
        int r0 = q0 + w16 + g, r1 = r0 + 8;
#pragma unroll
        for (int j = 0; j < 8; j++) {
            int col = j * 8 + 2 * t4;
            float2 o0 = { of[j][0] * inv0, of[j][1] * inv0 };
            float2 o1 = { of[j][2] * inv1, of[j][3] * inv1 };
            *(float2*)&O[base + (size_t)r0 * DMODEL + col] = o0;
            *(float2*)&O[base + (size_t)r1 * DMODEL + col] = o1;
        }
    }
}

// ---------------- launch ----------------
extern "C" void kernel_launch(void* const* d_in, const int* in_sizes, int n_in,
                              void* d_out, int out_size)
{
    const float* x  = (const float*)d_in[0];
    const float* wq = (const float*)d_in[1];
    const float* bq = (const float*)d_in[2];
    const float* wk = (const float*)d_in[3];
    const float* bk = (const float*)d_in[4];
    const float* wv = (const float*)d_in[5];
    const float* bv = (const float*)d_in[6];
    const float* wo = (const float*)d_in[7];
    const float* bo = (const float*)d_in[8];
    float* out = (float*)d_out;

    float *qb, *kb, *vb, *ab;
    cudaGetSymbolAddress((void**)&qb, g_q);
    cudaGetSymbolAddress((void**)&kb, g_k);
    cudaGetSymbolAddress((void**)&vb, g_v);
    cudaGetSymbolAddress((void**)&ab, g_attn);

    dim3 gdim(DMODEL / GBN, MTOT / GBM);   // (8, 32)
    gemm_nt_bias<<<gdim, 256>>>(x, wq, bq, qb, MTOT, DMODEL, DMODEL);
    gemm_nt_bias<<<gdim, 256>>>(x, wk, bk, kb, MTOT, DMODEL, DMODEL);
    gemm_nt_bias<<<gdim, 256>>>(x, wv, bv, vb, MTOT, DMODEL, DMODEL);

    const int smem_attn = SM_FL * (int)sizeof(float);   // 67584 B
    cudaFuncSetAttribute(attn_kernel, cudaFuncAttributeMaxDynamicSharedMemorySize, smem_attn);
    attn_kernel<<<dim3(NQT / 2, NHEAD, BATCH), 256, smem_attn>>>(qb, kb, vb, ab);

    gemm_nt_bias<<<gdim, 256>>>(ab, wo, bo, out, MTOT, DMODEL, DMODEL);
}

// round 11
// speedup vs baseline: 1.2792x; 1.0584x over previous
#include <cuda_runtime.h>
#include <cuda_bf16.h>
#include <math.h>

typedef unsigned int u32;

// Problem constants
#define BATCH 2
#define SEQ   2048
#define DMODEL 1024
#define NHEAD 16
#define HD    64
#define MTOT  (BATCH*SEQ)
#define NQT   (SEQ/128)

// ---------------- scratch ----------------
__device__ float g_q[BATCH*SEQ*DMODEL];
__device__ float g_k[BATCH*SEQ*DMODEL];
__device__ float g_v[BATCH*SEQ*DMODEL];
__device__ float g_attn[BATCH*SEQ*DMODEL];

// ---------------- helpers ----------------
__device__ __forceinline__ u32 f2tf(float x) {
    u32 u;
    asm("cvt.rna.tf32.f32 %0, %1;" : "=r"(u) : "f"(x));
    return u;
}
__device__ __forceinline__ float tfbits(float x) {
    return __uint_as_float(f2tf(x));
}
__device__ __forceinline__ void mma_tf32(float* d, const u32* a, const u32* b) {
    asm volatile(
        "mma.sync.aligned.m16n8k8.row.col.f32.tf32.tf32.f32 "
        "{%0,%1,%2,%3},{%4,%5,%6,%7},{%8,%9},{%0,%1,%2,%3};"
        : "+f"(d[0]), "+f"(d[1]), "+f"(d[2]), "+f"(d[3])
        : "r"(a[0]), "r"(a[1]), "r"(a[2]), "r"(a[3]), "r"(b[0]), "r"(b[1]));
}
__device__ __forceinline__ u32 ldsu(const float* p) {
    return __float_as_uint(*p);
}

// ---------------- GEMM: ping-pong smem, 1 sync/kb ----------------
#define GBM 128
#define GBN 128
#define GBK 32
#define GASTR 36
#define GSTAGE (GBM*GASTR)      // 4608 floats

__global__ __launch_bounds__(256, 2) void gemm_nt_bias(
    const float* __restrict__ A, const float* __restrict__ W,
    const float* __restrict__ bias, float* __restrict__ C,
    int M, int N, int K)
{
    extern __shared__ float gsm[];
    float* As = gsm;                 // 2 stages
    float* Ws = gsm + 2 * GSTAGE;

    const int tid  = threadIdx.x;
    const int warp = tid >> 5;
    const int lane = tid & 31;
    const int g    = lane >> 2;
    const int t4   = lane & 3;
    const int wm   = warp >> 2;
    const int wn   = warp & 3;
    const int m0   = blockIdx.y * GBM;
    const int n0   = blockIdx.x * GBN;

    float acc[4][4][4];
#pragma unroll
    for (int i = 0; i < 4; i++)
#pragma unroll
        for (int j = 0; j < 4; j++)
#pragma unroll
            for (int r = 0; r < 4; r++) acc[i][j][r] = 0.f;

    float4 ar[4], wr4[4];
    const int srow[4] = { (tid + 0)   >> 3, (tid + 256) >> 3,
                          (tid + 512) >> 3, (tid + 768) >> 3 };
    const int skq = (tid & 7) * 4;

    // prologue: load kb=0 into regs
#pragma unroll
    for (int l = 0; l < 4; l++) {
        ar[l]  = *(const float4*)&A[(size_t)(m0 + srow[l]) * K + skq];
        wr4[l] = *(const float4*)&W[(size_t)(n0 + srow[l]) * K + skq];
    }

    const int NKB = K / GBK;
    for (int kb = 0; kb < NKB; kb++) {
        const int buf = kb & 1;
        float* Ab = As + buf * GSTAGE;
        float* Wb = Ws + buf * GSTAGE;

        // STS stage kb (buf was last read at kb-2; fenced by kb-1's barrier)
#pragma unroll
        for (int l = 0; l < 4; l++) {
            float4 a4, w4;
            a4.x = tfbits(ar[l].x); a4.y = tfbits(ar[l].y);
            a4.z = tfbits(ar[l].z); a4.w = tfbits(ar[l].w);
            w4.x = tfbits(wr4[l].x); w4.y = tfbits(wr4[l].y);
            w4.z = tfbits(wr4[l].z); w4.w = tfbits(wr4[l].w);
            *(float4*)&Ab[srow[l] * GASTR + skq] = a4;
            *(float4*)&Wb[srow[l] * GASTR + skq] = w4;
        }

        // LDG stage kb+1
        if (kb + 1 < NKB) {
            int k0 = (kb + 1) * GBK;
#pragma unroll
            for (int l = 0; l < 4; l++) {
                ar[l]  = *(const float4*)&A[(size_t)(m0 + srow[l]) * K + k0 + skq];
                wr4[l] = *(const float4*)&W[(size_t)(n0 + srow[l]) * K + k0 + skq];
            }
        }

        __syncthreads();   // buf fully written; warps desync afterwards

        // compute from buf (overlaps with next iter's STS/LDG of other warps)
#pragma unroll
        for (int ks = 0; ks < 4; ks++) {
            const int k = ks * 8;
            u32 af[4][4], bf[4][2];
#pragma unroll
            for (int i = 0; i < 4; i++) {
                int rb = wm * 64 + i * 16 + g;
                af[i][0] = ldsu(&Ab[(rb)     * GASTR + k + t4]);
                af[i][1] = ldsu(&Ab[(rb + 8) * GASTR + k + t4]);
                af[i][2] = ldsu(&Ab[(rb)     * GASTR + k + t4 + 4]);
                af[i][3] = ldsu(&Ab[(rb + 8) * GASTR + k + t4 + 4]);
            }
#pragma unroll
            for (int j = 0; j < 4; j++) {
                int nb = wn * 32 + j * 8 + g;
                bf[j][0] = ldsu(&Wb[nb * GASTR + k + t4]);
                bf[j][1] = ldsu(&Wb[nb * GASTR + k + t4 + 4]);
            }
#pragma unroll
            for (int i = 0; i < 4; i++)
#pragma unroll
                for (int j = 0; j < 4; j++)
                    mma_tf32(acc[i][j], af[i], bf[j]);
        }
    }

    // epilogue: bias + store
#pragma unroll
    for (int j = 0; j < 4; j++) {
        int col = n0 + wn * 32 + j * 8 + 2 * t4;
        float b0 = bias[col], b1 = bias[col + 1];
#pragma unroll
        for (int i = 0; i < 4; i++) {
            int r0 = m0 + wm * 64 + i * 16 + g;
            float2 o0 = { acc[i][j][0] + b0, acc[i][j][1] + b1 };
            float2 o1 = { acc[i][j][2] + b0, acc[i][j][3] + b1 };
            *(float2*)&C[(size_t)r0 * N + col]       = o0;
            *(float2*)&C[(size_t)(r0 + 8) * N + col] = o1;
        }
    }
}

// ---------------- Flash attention (unchanged round-8 version) ----------------
#define QP_CH 132
#define KP_CH 66
#define SM_QP 0
#define SM_KP (64 * QP_CH)
#define SM_VP (SM_KP + 64 * KP_CH)
#define SM_FL (SM_VP + 64 * KP_CH)     // 16896 floats = 67584 B

__global__ __launch_bounds__(256, 2) void attn_kernel(
    const float* __restrict__ Q, const float* __restrict__ Kb,
    const float* __restrict__ Vb, float* __restrict__ O)
{
    extern __shared__ float sm[];
    float* Qp = sm + SM_QP;
    float* Kp = sm + SM_KP;
    float* Vp = sm + SM_VP;

    const int tid  = threadIdx.x;
    const int warp = tid >> 5;
    const int lane = tid & 31;
    const int g    = lane >> 2;
    const int t4   = lane & 3;

    const int h = blockIdx.y;
    const int b = blockIdx.z;
    const size_t base = ((size_t)b * SEQ) * DMODEL + (size_t)h * HD;
    const float scale = 0.125f;
    const int w16 = warp * 16;

    const int srcA = (lane & ~3) | (t4 >> 1);
    const int srcB = srcA + 2;
    const bool odd = (t4 & 1) != 0;

    for (int half = 0; half < 2; half++) {
        const int qtile = half ? (int)blockIdx.x : (NQT - 1 - (int)blockIdx.x);
        const int q0 = qtile * 128;

        __syncthreads();

#pragma unroll
        for (int l = 0; l < 8; l++) {
            int f4  = tid + l * 256;
            int row = f4 >> 4;
            int col = (f4 & 15) * 4;
            float4 v = *(const float4*)&Q[base + (size_t)(q0 + row) * DMODEL + col];
            int wb = row >> 4, r8 = (row >> 3) & 1, gg = row & 7;
            int ks = col >> 3, hf = (col >> 2) & 1;
            float* dst = &Qp[(wb * 8 + ks) * QP_CH + r8 + 2 * hf];
            dst[(gg * 4 + 0) * 4] = tfbits(v.x * scale);
            dst[(gg * 4 + 1) * 4] = tfbits(v.y * scale);
            dst[(gg * 4 + 2) * 4] = tfbits(v.z * scale);
            dst[(gg * 4 + 3) * 4] = tfbits(v.w * scale);
        }

        float of[8][4];
#pragma unroll
        for (int j = 0; j < 8; j++)
#pragma unroll
            for (int r = 0; r < 4; r++) of[j][r] = 0.f;
        float m0r = -1e30f, m1r = -1e30f, l0r = 0.f, l1r = 0.f;

        const int ntiles = 2 * qtile + 2;

        for (int jt = 0; jt < ntiles; jt++) {
            __syncthreads();
#pragma unroll
            for (int l = 0; l < 4; l++) {
                int f4  = tid + l * 256;
                int row = f4 >> 4;
                int col = (f4 & 15) * 4;
                size_t gaddr = base + (size_t)(jt * 64 + row) * DMODEL + col;

                float4 kv = *(const float4*)&Kb[gaddr];
                {
                    int j = row >> 3, gg = row & 7;
                    int ks = col >> 3, hf = (col >> 2) & 1;
                    float* kd = &Kp[(j * 8 + ks) * KP_CH + hf];
                    kd[(gg * 4 + 0) * 2] = tfbits(kv.x);
                    kd[(gg * 4 + 1) * 2] = tfbits(kv.y);
                    kd[(gg * 4 + 2) * 2] = tfbits(kv.z);
                    kd[(gg * 4 + 3) * 2] = tfbits(kv.w);
                }
                float4 vv = *(const float4*)&Vb[gaddr];
                {
                    int ks = row >> 3, tt = row & 3;
                    int j = col >> 3, g0 = col & 7;
                    float* vd = &Vp[(ks * 8 + j) * KP_CH + ((row >> 2) & 1)];
                    vd[((g0 + 0) * 4 + tt) * 2] = tfbits(vv.x);
                    vd[((g0 + 1) * 4 + tt) * 2] = tfbits(vv.y);
                    vd[((g0 + 2) * 4 + tt) * 2] = tfbits(vv.z);
                    vd[((g0 + 3) * 4 + tt) * 2] = tfbits(vv.w);
                }
            }
            __syncthreads();

            float s[8][4];
#pragma unroll
            for (int j = 0; j < 8; j++)
#pragma unroll
                for (int r = 0; r < 4; r++) s[j][r] = 0.f;

#pragma unroll
            for (int ks = 0; ks < 8; ks++) {
                float4 aq = *(const float4*)&Qp[(warp * 8 + ks) * QP_CH + lane * 4];
                u32 a[4] = { __float_as_uint(aq.x), __float_as_uint(aq.y),
                             __float_as_uint(aq.z), __float_as_uint(aq.w) };
#pragma unroll
                for (int j = 0; j < 8; j++) {
                    float2 kf = *(const float2*)&Kp[(j * 8 + ks) * KP_CH + lane * 2];
                    u32 bfr[2] = { __float_as_uint(kf.x), __float_as_uint(kf.y) };
                    mma_tf32(s[j], a, bfr);
                }
            }

            if (jt >= 2 * qtile) {
                int r0 = q0 + w16 + g, r1 = r0 + 8;
#pragma unroll
                for (int j = 0; j < 8; j++) {
                    int c = jt * 64 + j * 8 + 2 * t4;
                    if (c     > r0) s[j][0] = -1e30f;
                    if (c + 1 > r0) s[j][1] = -1e30f;
                    if (c     > r1) s[j][2] = -1e30f;
                    if (c + 1 > r1) s[j][3] = -1e30f;
                }
            }

            float mt0 = -1e30f, mt1 = -1e30f;
#pragma unroll
            for (int j = 0; j < 8; j++) {
                mt0 = fmaxf(mt0, fmaxf(s[j][0], s[j][1]));
                mt1 = fmaxf(mt1, fmaxf(s[j][2], s[j][3]));
            }
            mt0 = fmaxf(mt0, __shfl_xor_sync(0xffffffffu, mt0, 1));
            mt0 = fmaxf(mt0, __shfl_xor_sync(0xffffffffu, mt0, 2));
            mt1 = fmaxf(mt1, __shfl_xor_sync(0xffffffffu, mt1, 1));
            mt1 = fmaxf(mt1, __shfl_xor_sync(0xffffffffu, mt1, 2));

            float mn0 = fmaxf(m0r, mt0), mn1 = fmaxf(m1r, mt1);
            float corr0 = __expf(m0r - mn0), corr1 = __expf(m1r - mn1);
            m0r = mn0; m1r = mn1;

            float ps0 = 0.f, ps1 = 0.f;
#pragma unroll
            for (int j = 0; j < 8; j++) {
                s[j][0] = __expf(s[j][0] - mn0); ps0 += s[j][0];
                s[j][1] = __expf(s[j][1] - mn0); ps0 += s[j][1];
                s[j][2] = __expf(s[j][2] - mn1); ps1 += s[j][2];
                s[j][3] = __expf(s[j][3] - mn1); ps1 += s[j][3];
            }
            ps0 += __shfl_xor_sync(0xffffffffu, ps0, 1);
            ps0 += __shfl_xor_sync(0xffffffffu, ps0, 2);
            ps1 += __shfl_xor_sync(0xffffffffu, ps1, 1);
            ps1 += __shfl_xor_sync(0xffffffffu, ps1, 2);
            l0r = l0r * corr0 + ps0;
            l1r = l1r * corr1 + ps1;

#pragma unroll
            for (int j = 0; j < 8; j++) {
                of[j][0] *= corr0; of[j][1] *= corr0;
                of[j][2] *= corr1; of[j][3] *= corr1;
            }

#pragma unroll
            for (int j = 0; j < 8; j++) {
                s[j][0] = tfbits(s[j][0]); s[j][1] = tfbits(s[j][1]);
                s[j][2] = tfbits(s[j][2]); s[j][3] = tfbits(s[j][3]);
            }

#pragma unroll
            for (int ks = 0; ks < 8; ks++) {
                float v0 = __shfl_sync(0xffffffffu, s[ks][0], srcA);
                float v1 = __shfl_sync(0xffffffffu, s[ks][1], srcA);
                float v2 = __shfl_sync(0xffffffffu, s[ks][2], srcA);
                float v3 = __shfl_sync(0xffffffffu, s[ks][3], srcA);
                float w0 = __shfl_sync(0xffffffffu, s[ks][0], srcB);
                float w1 = __shfl_sync(0xffffffffu, s[ks][1], srcB);
                float w2 = __shfl_sync(0xffffffffu, s[ks][2], srcB);
                float w3 = __shfl_sync(0xffffffffu, s[ks][3], srcB);
                u32 pa[4];
                pa[0] = __float_as_uint(odd ? v1 : v0);
                pa[1] = __float_as_uint(odd ? v3 : v2);
                pa[2] = __float_as_uint(odd ? w1 : w0);
                pa[3] = __float_as_uint(odd ? w3 : w2);
#pragma unroll
                for (int j = 0; j < 8; j++) {
                    float2 vf = *(const float2*)&Vp[(ks * 8 + j) * KP_CH + lane * 2];
                    u32 bfr[2] = { __float_as_uint(vf.x), __float_as_uint(vf.y) };
                    mma_tf32(of[j], pa, bfr);
                }
            }
        }

        float inv0 = 1.f / l0r, inv1 = 1.f / l1r;
        int r0 = q0 + w16 + g, r1 = r0 + 8;
#pragma unroll
        for (int j = 0; j < 8; j++) {
            int col = j * 8 + 2 * t4;
            float2 o0 = { of[j][0] * inv0, of[j][1] * inv0 };
            float2 o1 = { of[j][2] * inv1, of[j][3] * inv1 };
            *(float2*)&O[base + (size_t)r0 * DMODEL + col] = o0;
            *(float2*)&O[base + (size_t)r1 * DMODEL + col] = o1;
        }
    }
}

// ---------------- launch ----------------
extern "C" void kernel_launch(void* const* d_in, const int* in_sizes, int n_in,
                              void* d_out, int out_size)
{
    const float* x  = (const float*)d_in[0];
    const float* wq = (const float*)d_in[1];
    const float* bq = (const float*)d_in[2];
    const float* wk = (const float*)d_in[3];
    const float* bk = (const float*)d_in[4];
    const float* wv = (const float*)d_in[5];
    const float* bv = (const float*)d_in[6];
    const float* wo = (const float*)d_in[7];
    const float* bo = (const float*)d_in[8];
    float* out = (float*)d_out;

    float *qb, *kb, *vb, *ab;
    cudaGetSymbolAddress((void**)&qb, g_q);
    cudaGetSymbolAddress((void**)&kb, g_k);
    cudaGetSymbolAddress((void**)&vb, g_v);
    cudaGetSymbolAddress((void**)&ab, g_attn);

    const int smem_gemm = 4 * GSTAGE * (int)sizeof(float);   // 73728 B
    cudaFuncSetAttribute(gemm_nt_bias, cudaFuncAttributeMaxDynamicSharedMemorySize, smem_gemm);

    dim3 gdim(DMODEL / GBN, MTOT / GBM);   // (8, 32)
    gemm_nt_bias<<<gdim, 256, smem_gemm>>>(x, wq, bq, qb, MTOT, DMODEL, DMODEL);
    gemm_nt_bias<<<gdim, 256, smem_gemm>>>(x, wk, bk, kb, MTOT, DMODEL, DMODEL);
    gemm_nt_bias<<<gdim, 256, smem_gemm>>>(x, wv, bv, vb, MTOT, DMODEL, DMODEL);

    const int smem_attn = SM_FL * (int)sizeof(float);   // 67584 B
    cudaFuncSetAttribute(attn_kernel, cudaFuncAttributeMaxDynamicSharedMemorySize, smem_attn);
    attn_kernel<<<dim3(NQT / 2, NHEAD, BATCH), 256, smem_attn>>>(qb, kb, vb, ab);

    gemm_nt_bias<<<gdim, 256, smem_gemm>>>(ab, wo, bo, out, MTOT, DMODEL, DMODEL);
}

// round 13
// speedup vs baseline: 1.2907x; 1.0090x over previous
#include <cuda_runtime.h>
#include <cuda_bf16.h>
#include <math.h>

typedef unsigned int u32;

// Problem constants
#define BATCH 2
#define SEQ   2048
#define DMODEL 1024
#define NHEAD 16
#define HD    64
#define MTOT  (BATCH*SEQ)
#define NQT   (SEQ/128)

// ---------------- scratch ----------------
__device__ float g_q[BATCH*SEQ*DMODEL];
__device__ float g_k[BATCH*SEQ*DMODEL];
__device__ float g_v[BATCH*SEQ*DMODEL];
__device__ float g_attn[BATCH*SEQ*DMODEL];

// ---------------- helpers ----------------
__device__ __forceinline__ u32 f2tf(float x) {
    u32 u;
    asm("cvt.rna.tf32.f32 %0, %1;" : "=r"(u) : "f"(x));
    return u;
}
__device__ __forceinline__ float tfbits(float x) {
    return __uint_as_float(f2tf(x));
}
__device__ __forceinline__ void mma_tf32(float* d, const u32* a, const u32* b) {
    asm volatile(
        "mma.sync.aligned.m16n8k8.row.col.f32.tf32.tf32.f32 "
        "{%0,%1,%2,%3},{%4,%5,%6,%7},{%8,%9},{%0,%1,%2,%3};"
        : "+f"(d[0]), "+f"(d[1]), "+f"(d[2]), "+f"(d[3])
        : "r"(a[0]), "r"(a[1]), "r"(a[2]), "r"(a[3]), "r"(b[0]), "r"(b[1]));
}
__device__ __forceinline__ u32 ldsu(const float* p) {
    return __float_as_uint(*p);
}

// ---------------- GEMM: 128x256 block tile, 64x64 warp tile, ping-pong smem ----------------
#define GBM 128
#define GBN 256
#define GBK 32
#define GASTR 36
#define GASTAGE (GBM*GASTR)     // 4608 floats per A stage
#define GWSTAGE (GBN*GASTR)     // 9216 floats per W stage

__global__ __launch_bounds__(256, 1) void gemm_nt_bias(
    const float* __restrict__ A, const float* __restrict__ W,
    const float* __restrict__ bias, float* __restrict__ C,
    int M, int N, int K)
{
    extern __shared__ float gsm[];
    float* As = gsm;                     // 2 stages of A
    float* Ws = gsm + 2 * GASTAGE;       // 2 stages of W

    const int tid  = threadIdx.x;
    const int warp = tid >> 5;
    const int lane = tid & 31;
    const int g    = lane >> 2;
    const int t4   = lane & 3;
    const int wm   = warp >> 2;   // 0..1  (M)
    const int wn   = warp & 3;    // 0..3  (N)
    const int m0   = blockIdx.y * GBM;
    const int n0   = blockIdx.x * GBN;

    float acc[4][8][4];
#pragma unroll
    for (int i = 0; i < 4; i++)
#pragma unroll
        for (int j = 0; j < 8; j++)
#pragma unroll
            for (int r = 0; r < 4; r++) acc[i][j][r] = 0.f;

    // staging: A 4 float4 (rows via srow), W 8 float4 (rows via same pattern, 256 rows)
    float4 ar[4], wr4[8];
    const int skq = (tid & 7) * 4;
    int srA[4], srW[8];
#pragma unroll
    for (int l = 0; l < 4; l++) srA[l] = (tid + 256 * l) >> 3;    // 0..127
#pragma unroll
    for (int l = 0; l < 8; l++) srW[l] = (tid + 256 * l) >> 3;    // 0..255

    // prologue: load kb=0
#pragma unroll
    for (int l = 0; l < 4; l++)
        ar[l] = *(const float4*)&A[(size_t)(m0 + srA[l]) * K + skq];
#pragma unroll
    for (int l = 0; l < 8; l++)
        wr4[l] = *(const float4*)&W[(size_t)(n0 + srW[l]) * K + skq];

    const int NKB = K / GBK;   // 32
    for (int kb = 0; kb < NKB; kb++) {
        const int buf = kb & 1;
        float* Ab = As + buf * GASTAGE;
        float* Wb = Ws + buf * GWSTAGE;

        // STS stage kb (tf32-rounded)
#pragma unroll
        for (int l = 0; l < 4; l++) {
            float4 a4;
            a4.x = tfbits(ar[l].x); a4.y = tfbits(ar[l].y);
            a4.z = tfbits(ar[l].z); a4.w = tfbits(ar[l].w);
            *(float4*)&Ab[srA[l] * GASTR + skq] = a4;
        }
#pragma unroll
        for (int l = 0; l < 8; l++) {
            float4 w4;
            w4.x = tfbits(wr4[l].x); w4.y = tfbits(wr4[l].y);
            w4.z = tfbits(wr4[l].z); w4.w = tfbits(wr4[l].w);
            *(float4*)&Wb[srW[l] * GASTR + skq] = w4;
        }

        // LDG stage kb+1
        if (kb + 1 < NKB) {
            int k0 = (kb + 1) * GBK;
#pragma unroll
            for (int l = 0; l < 4; l++)
                ar[l] = *(const float4*)&A[(size_t)(m0 + srA[l]) * K + k0 + skq];
#pragma unroll
            for (int l = 0; l < 8; l++)
                wr4[l] = *(const float4*)&W[(size_t)(n0 + srW[l]) * K + k0 + skq];
        }

        __syncthreads();

        // compute from buf
#pragma unroll
        for (int ks = 0; ks < 4; ks++) {
            const int k = ks * 8;
            u32 af[4][4];
#pragma unroll
            for (int i = 0; i < 4; i++) {
                int rb = wm * 64 + i * 16 + g;
                af[i][0] = ldsu(&Ab[(rb)     * GASTR + k + t4]);
                af[i][1] = ldsu(&Ab[(rb + 8) * GASTR + k + t4]);
                af[i][2] = ldsu(&Ab[(rb)     * GASTR + k + t4 + 4]);
                af[i][3] = ldsu(&Ab[(rb + 8) * GASTR + k + t4 + 4]);
            }
#pragma unroll
            for (int j = 0; j < 8; j++) {
                int nb = wn * 64 + j * 8 + g;
                u32 bf[2];
                bf[0] = ldsu(&Wb[nb * GASTR + k + t4]);
                bf[1] = ldsu(&Wb[nb * GASTR + k + t4 + 4]);
#pragma unroll
                for (int i = 0; i < 4; i++)
                    mma_tf32(acc[i][j], af[i], bf);
            }
        }
        __syncthreads();   // all reads of buf done before it's overwritten at kb+2
    }

    // epilogue: bias + store
#pragma unroll
    for (int j = 0; j < 8; j++) {
        int col = n0 + wn * 64 + j * 8 + 2 * t4;
        float b0 = bias[col], b1 = bias[col + 1];
#pragma unroll
        for (int i = 0; i < 4; i++) {
            int r0 = m0 + wm * 64 + i * 16 + g;
            float2 o0 = { acc[i][j][0] + b0, acc[i][j][1] + b1 };
            float2 o1 = { acc[i][j][2] + b0, acc[i][j][3] + b1 };
            *(float2*)&C[(size_t)r0 * N + col]       = o0;
            *(float2*)&C[(size_t)(r0 + 8) * N + col] = o1;
        }
    }
}

// ---------------- Flash attention (unchanged round-8/11 version) ----------------
#define QP_CH 132
#define KP_CH 66
#define SM_QP 0
#define SM_KP (64 * QP_CH)
#define SM_VP (SM_KP + 64 * KP_CH)
#define SM_FL (SM_VP + 64 * KP_CH)     // 16896 floats = 67584 B

__global__ __launch_bounds__(256, 2) void attn_kernel(
    const float* __restrict__ Q, const float* __restrict__ Kb,
    const float* __restrict__ Vb, float* __restrict__ O)
{
    extern __shared__ float sm[];
    float* Qp = sm + SM_QP;
    float* Kp = sm + SM_KP;
    float* Vp = sm + SM_VP;

    const int tid  = threadIdx.x;
    const int warp = tid >> 5;
    const int lane = tid & 31;
    const int g    = lane >> 2;
    const int t4   = lane & 3;

    const int h = blockIdx.y;
    const int b = blockIdx.z;
    const size_t base = ((size_t)b * SEQ) * DMODEL + (size_t)h * HD;
    const float scale = 0.125f;
    const int w16 = warp * 16;

    const int srcA = (lane & ~3) | (t4 >> 1);
    const int srcB = srcA + 2;
    const bool odd = (t4 & 1) != 0;

    for (int half = 0; half < 2; half++) {
        const int qtile = half ? (int)blockIdx.x : (NQT - 1 - (int)blockIdx.x);
        const int q0 = qtile * 128;

        __syncthreads();

#pragma unroll
        for (int l = 0; l < 8; l++) {
            int f4  = tid + l * 256;
            int row = f4 >> 4;
            int col = (f4 & 15) * 4;
            float4 v = *(const float4*)&Q[base + (size_t)(q0 + row) * DMODEL + col];
            int wb = row >> 4, r8 = (row >> 3) & 1, gg = row & 7;
            int ks = col >> 3, hf = (col >> 2) & 1;
            float* dst = &Qp[(wb * 8 + ks) * QP_CH + r8 + 2 * hf];
            dst[(gg * 4 + 0) * 4] = tfbits(v.x * scale);
            dst[(gg * 4 + 1) * 4] = tfbits(v.y * scale);
            dst[(gg * 4 + 2) * 4] = tfbits(v.z * scale);
            dst[(gg * 4 + 3) * 4] = tfbits(v.w * scale);
        }

        float of[8][4];
#pragma unroll
        for (int j = 0; j < 8; j++)
#pragma unroll
            for (int r = 0; r < 4; r++) of[j][r] = 0.f;
        float m0r = -1e30f, m1r = -1e30f, l0r = 0.f, l1r = 0.f;

        const int ntiles = 2 * qtile + 2;

        for (int jt = 0; jt < ntiles; jt++) {
            __syncthreads();
#pragma unroll
            for (int l = 0; l < 4; l++) {
                int f4  = tid + l * 256;
                int row = f4 >> 4;
                int col = (f4 & 15) * 4;
                size_t gaddr = base + (size_t)(jt * 64 + row) * DMODEL + col;

                float4 kv = *(const float4*)&Kb[gaddr];
                {
                    int j = row >> 3, gg = row & 7;
                    int ks = col >> 3, hf = (col >> 2) & 1;
                    float* kd = &Kp[(j * 8 + ks) * KP_CH + hf];
                    kd[(gg * 4 + 0) * 2] = tfbits(kv.x);
                    kd[(gg * 4 + 1) * 2] = tfbits(kv.y);
                    kd[(gg * 4 + 2) * 2] = tfbits(kv.z);
                    kd[(gg * 4 + 3) * 2] = tfbits(kv.w);
                }
                float4 vv = *(const float4*)&Vb[gaddr];
                {
                    int ks = row >> 3, tt = row & 3;
                    int j = col >> 3, g0 = col & 7;
                    float* vd = &Vp[(ks * 8 + j) * KP_CH + ((row >> 2) & 1)];
                    vd[((g0 + 0) * 4 + tt) * 2] = tfbits(vv.x);
                    vd[((g0 + 1) * 4 + tt) * 2] = tfbits(vv.y);
                    vd[((g0 + 2) * 4 + tt) * 2] = tfbits(vv.z);
                    vd[((g0 + 3) * 4 + tt) * 2] = tfbits(vv.w);
                }
            }
            __syncthreads();

            float s[8][4];
#pragma unroll
            for (int j = 0; j < 8; j++)
#pragma unroll
                for (int r = 0; r < 4; r++) s[j][r] = 0.f;

#pragma unroll
            for (int ks = 0; ks < 8; ks++) {
                float4 aq = *(const float4*)&Qp[(warp * 8 + ks) * QP_CH + lane * 4];
                u32 a[4] = { __float_as_uint(aq.x), __float_as_uint(aq.y),
                             __float_as_uint(aq.z), __float_as_uint(aq.w) };
#pragma unroll
                for (int j = 0; j < 8; j++) {
                    float2 kf = *(const float2*)&Kp[(j * 8 + ks) * KP_CH + lane * 2];
                    u32 bfr[2] = { __float_as_uint(kf.x), __float_as_uint(kf.y) };
                    mma_tf32(s[j], a, bfr);
                }
            }

            if (jt >= 2 * qtile) {
                int r0 = q0 + w16 + g, r1 = r0 + 8;
#pragma unroll
                for (int j = 0; j < 8; j++) {
                    int c = jt * 64 + j * 8 + 2 * t4;
                    if (c     > r0) s[j][0] = -1e30f;
                    if (c + 1 > r0) s[j][1] = -1e30f;
                    if (c     > r1) s[j][2] = -1e30f;
                    if (c + 1 > r1) s[j][3] = -1e30f;
                }
            }

            float mt0 = -1e30f, mt1 = -1e30f;
#pragma unroll
            for (int j = 0; j < 8; j++) {
                mt0 = fmaxf(mt0, fmaxf(s[j][0], s[j][1]));
                mt1 = fmaxf(mt1, fmaxf(s[j][2], s[j][3]));
            }
            mt0 = fmaxf(mt0, __shfl_xor_sync(0xffffffffu, mt0, 1));
            mt0 = fmaxf(mt0, __shfl_xor_sync(0xffffffffu, mt0, 2));
            mt1 = fmaxf(mt1, __shfl_xor_sync(0xffffffffu, mt1, 1));
            mt1 = fmaxf(mt1, __shfl_xor_sync(0xffffffffu, mt1, 2));

            float mn0 = fmaxf(m0r, mt0), mn1 = fmaxf(m1r, mt1);
            float corr0 = __expf(m0r - mn0), corr1 = __expf(m1r - mn1);
            m0r = mn0; m1r = mn1;

            float ps0 = 0.f, ps1 = 0.f;
#pragma unroll
            for (int j = 0; j < 8; j++) {
                s[j][0] = __expf(s[j][0] - mn0); ps0 += s[j][0];
                s[j][1] = __expf(s[j][1] - mn0); ps0 += s[j][1];
                s[j][2] = __expf(s[j][2] - mn1); ps1 += s[j][2];
                s[j][3] = __expf(s[j][3] - mn1); ps1 += s[j][3];
            }
            ps0 += __shfl_xor_sync(0xffffffffu, ps0, 1);
            ps0 += __shfl_xor_sync(0xffffffffu, ps0, 2);
            ps1 += __shfl_xor_sync(0xffffffffu, ps1, 1);
            ps1 += __shfl_xor_sync(0xffffffffu, ps1, 2);
            l0r = l0r * corr0 + ps0;
            l1r = l1r * corr1 + ps1;

#pragma unroll
            for (int j = 0; j < 8; j++) {
                of[j][0] *= corr0; of[j][1] *= corr0;
                of[j][2] *= corr1; of[j][3] *= corr1;
            }

#pragma unroll
            for (int j = 0; j < 8; j++) {
                s[j][0] = tfbits(s[j][0]); s[j][1] = tfbits(s[j][1]);
                s[j][2] = tfbits(s[j][2]); s[j][3] = tfbits(s[j][3]);
            }

#pragma unroll
            for (int ks = 0; ks < 8; ks++) {
                float v0 = __shfl_sync(0xffffffffu, s[ks][0], srcA);
                float v1 = __shfl_sync(0xffffffffu, s[ks][1], srcA);
                float v2 = __shfl_sync(0xffffffffu, s[ks][2], srcA);
                float v3 = __shfl_sync(0xffffffffu, s[ks][3], srcA);
                float w0 = __shfl_sync(0xffffffffu, s[ks][0], srcB);
                float w1 = __shfl_sync(0xffffffffu, s[ks][1], srcB);
                float w2 = __shfl_sync(0xffffffffu, s[ks][2], srcB);
                float w3 = __shfl_sync(0xffffffffu, s[ks][3], srcB);
                u32 pa[4];
                pa[0] = __float_as_uint(odd ? v1 : v0);
                pa[1] = __float_as_uint(odd ? v3 : v2);
                pa[2] = __float_as_uint(odd ? w1 : w0);
                pa[3] = __float_as_uint(odd ? w3 : w2);
#pragma unroll
                for (int j = 0; j < 8; j++) {
                    float2 vf = *(const float2*)&Vp[(ks * 8 + j) * KP_CH + lane * 2];
                    u32 bfr[2] = { __float_as_uint(vf.x), __float_as_uint(vf.y) };
                    mma_tf32(of[j], pa, bfr);
                }
            }
        }

        float inv0 = 1.f / l0r, inv1 = 1.f / l1r;
        int r0 = q0 + w16 + g, r1 = r0 + 8;
#pragma unroll
        for (int j = 0; j < 8; j++) {
            int col = j * 8 + 2 * t4;
            float2 o0 = { of[j][0] * inv0, of[j][1] * inv0 };
            float2 o1 = { of[j][2] * inv1, of[j][3] * inv1 };
            *(float2*)&O[base + (size_t)r0 * DMODEL + col] = o0;
            *(float2*)&O[base + (size_t)r1 * DMODEL + col] = o1;
        }
    }
}

// ---------------- launch ----------------
extern "C" void kernel_launch(void* const* d_in, const int* in_sizes, int n_in,
                              void* d_out, int out_size)
{
    const float* x  = (const float*)d_in[0];
    const float* wq = (const float*)d_in[1];
    const float* bq = (const float*)d_in[2];
    const float* wk = (const float*)d_in[3];
    const float* bk = (const float*)d_in[4];
    const float* wv = (const float*)d_in[5];
    const float* bv = (const float*)d_in[6];
    const float* wo = (const float*)d_in[7];
    const float* bo = (const float*)d_in[8];
    float* out = (float*)d_out;

    float *qb, *kb, *vb, *ab;
    cudaGetSymbolAddress((void**)&qb, g_q);
    cudaGetSymbolAddress((void**)&kb, g_k);
    cudaGetSymbolAddress((void**)&vb, g_v);
    cudaGetSymbolAddress((void**)&ab, g_attn);

    const int smem_gemm = (2 * GASTAGE + 2 * GWSTAGE) * (int)sizeof(float);  // 110592 B
    cudaFuncSetAttribute(gemm_nt_bias, cudaFuncAttributeMaxDynamicSharedMemorySize, smem_gemm);

    dim3 gdim(DMODEL / GBN, MTOT / GBM);   // (4, 32) = 128 blocks
    gemm_nt_bias<<<gdim, 256, smem_gemm>>>(x, wq, bq, qb, MTOT, DMODEL, DMODEL);
    gemm_nt_bias<<<gdim, 256, smem_gemm>>>(x, wk, bk, kb, MTOT, DMODEL, DMODEL);
    gemm_nt_bias<<<gdim, 256, smem_gemm>>>(x, wv, bv, vb, MTOT, DMODEL, DMODEL);

    const int smem_attn = SM_FL * (int)sizeof(float);   // 67584 B
    cudaFuncSetAttribute(attn_kernel, cudaFuncAttributeMaxDynamicSharedMemorySize, smem_attn);
    attn_kernel<<<dim3(NQT / 2, NHEAD, BATCH), 256, smem_attn>>>(qb, kb, vb, ab);

    gemm_nt_bias<<<gdim, 256, smem_gemm>>>(ab, wo, bo, out, MTOT, DMODEL, DMODEL);
}

// round 15
// speedup vs baseline: 1.8608x; 1.4417x over previous
#include <cuda_runtime.h>
#include <cuda_fp16.h>
#include <math.h>

typedef unsigned int u32;

// Problem constants
#define BATCH 2
#define SEQ   2048
#define DMODEL 1024
#define NHEAD 16
#define HD    64
#define MTOT  (BATCH*SEQ)
#define NQT   (SEQ/128)

// ---------------- scratch ----------------
__device__ float g_q[BATCH*SEQ*DMODEL];
__device__ float g_k[BATCH*SEQ*DMODEL];
__device__ float g_v[BATCH*SEQ*DMODEL];
__device__ float g_attn[BATCH*SEQ*DMODEL];

// ---------------- helpers ----------------
__device__ __forceinline__ u32 pack_h2(float a, float b) {
    __half2 h = __floats2half2_rn(a, b);   // lo = a, hi = b
    return *(u32*)&h;
}
__device__ __forceinline__ void mma_f16(float* d, const u32* a, const u32* b) {
    asm volatile(
        "mma.sync.aligned.m16n8k16.row.col.f32.f16.f16.f32 "
        "{%0,%1,%2,%3},{%4,%5,%6,%7},{%8,%9},{%0,%1,%2,%3};"
        : "+f"(d[0]), "+f"(d[1]), "+f"(d[2]), "+f"(d[3])
        : "r"(a[0]), "r"(a[1]), "r"(a[2]), "r"(a[3]), "r"(b[0]), "r"(b[1]));
}
__device__ __forceinline__ u32 ldh2(const __half* p) {
    return *(const u32*)p;
}

// ---------------- GEMM: fp16 mma, 128x256 tile, 64x64 warp tile, ping-pong ----------------
#define GBM 128
#define GBN 256
#define GBK 32
#define AHS 40                    // row stride in halves (80 B) -> conflict-free frags
#define AHSTG (GBM*AHS)           // 5120 halves per A stage
#define WHSTG (GBN*AHS)           // 10240 halves per W stage

__global__ __launch_bounds__(256, 1) void gemm_h(
    const float* __restrict__ A, const float* __restrict__ W,
    const float* __restrict__ bias, float* __restrict__ C,
    int M, int N, int K)
{
    extern __shared__ __half hsm[];
    __half* Ah = hsm;                  // 2 stages
    __half* Wh = hsm + 2 * AHSTG;

    const int tid  = threadIdx.x;
    const int warp = tid >> 5;
    const int lane = tid & 31;
    const int g    = lane >> 2;
    const int t4   = lane & 3;
    const int wm   = warp >> 2;   // 0..1 (M)
    const int wn   = warp & 3;    // 0..3 (N)
    const int m0   = blockIdx.y * GBM;
    const int n0   = blockIdx.x * GBN;

    float acc[4][8][4];
#pragma unroll
    for (int i = 0; i < 4; i++)
#pragma unroll
        for (int j = 0; j < 8; j++)
#pragma unroll
            for (int r = 0; r < 4; r++) acc[i][j][r] = 0.f;

    float4 ar[4], wr4[8];
    const int skq = (tid & 7) * 4;      // k-offset (floats == halves*1 here: 4 floats)
    int srA[4], srW[8];
#pragma unroll
    for (int l = 0; l < 4; l++) srA[l] = (tid + 256 * l) >> 3;    // 0..127
#pragma unroll
    for (int l = 0; l < 8; l++) srW[l] = (tid + 256 * l) >> 3;    // 0..255

    // prologue: load kb=0
#pragma unroll
    for (int l = 0; l < 4; l++)
        ar[l] = *(const float4*)&A[(size_t)(m0 + srA[l]) * K + skq];
#pragma unroll
    for (int l = 0; l < 8; l++)
        wr4[l] = *(const float4*)&W[(size_t)(n0 + srW[l]) * K + skq];

    const int NKB = K / GBK;   // 32
    for (int kb = 0; kb < NKB; kb++) {
        const int buf = kb & 1;
        __half* Ab = Ah + buf * AHSTG;
        __half* Wb = Wh + buf * WHSTG;

        // STS stage kb (fp32 -> half2 pairs, 8B stores)
#pragma unroll
        for (int l = 0; l < 4; l++) {
            uint2 u;
            u.x = pack_h2(ar[l].x, ar[l].y);
            u.y = pack_h2(ar[l].z, ar[l].w);
            *(uint2*)&Ab[srA[l] * AHS + skq] = u;
        }
#pragma unroll
        for (int l = 0; l < 8; l++) {
            uint2 u;
            u.x = pack_h2(wr4[l].x, wr4[l].y);
            u.y = pack_h2(wr4[l].z, wr4[l].w);
            *(uint2*)&Wb[srW[l] * AHS + skq] = u;
        }

        // LDG stage kb+1
        if (kb + 1 < NKB) {
            int k0 = (kb + 1) * GBK;
#pragma unroll
            for (int l = 0; l < 4; l++)
                ar[l] = *(const float4*)&A[(size_t)(m0 + srA[l]) * K + k0 + skq];
#pragma unroll
            for (int l = 0; l < 8; l++)
                wr4[l] = *(const float4*)&W[(size_t)(n0 + srW[l]) * K + k0 + skq];
        }

        __syncthreads();

        // compute: 2 K=16 steps per 32-chunk
#pragma unroll
        for (int ks = 0; ks < 2; ks++) {
            const int k0 = ks * 16;
            u32 af[4][4];
#pragma unroll
            for (int i = 0; i < 4; i++) {
                int rb = wm * 64 + i * 16 + g;
                af[i][0] = ldh2(&Ab[(rb)     * AHS + k0 + 2 * t4]);
                af[i][1] = ldh2(&Ab[(rb + 8) * AHS + k0 + 2 * t4]);
                af[i][2] = ldh2(&Ab[(rb)     * AHS + k0 + 2 * t4 + 8]);
                af[i][3] = ldh2(&Ab[(rb + 8) * AHS + k0 + 2 * t4 + 8]);
            }
#pragma unroll
            for (int j = 0; j < 8; j++) {
                int nb = wn * 64 + j * 8 + g;
                u32 bf[2];
                bf[0] = ldh2(&Wb[nb * AHS + k0 + 2 * t4]);
                bf[1] = ldh2(&Wb[nb * AHS + k0 + 2 * t4 + 8]);
#pragma unroll
                for (int i = 0; i < 4; i++)
                    mma_f16(acc[i][j], af[i], bf);
            }
        }
        __syncthreads();
    }

    // epilogue: bias + store
#pragma unroll
    for (int j = 0; j < 8; j++) {
        int col = n0 + wn * 64 + j * 8 + 2 * t4;
        float b0 = bias[col], b1 = bias[col + 1];
#pragma unroll
        for (int i = 0; i < 4; i++) {
            int r0 = m0 + wm * 64 + i * 16 + g;
            float2 o0 = { acc[i][j][0] + b0, acc[i][j][1] + b1 };
            float2 o1 = { acc[i][j][2] + b0, acc[i][j][3] + b1 };
            *(float2*)&C[(size_t)r0 * N + col]       = o0;
            *(float2*)&C[(size_t)(r0 + 8) * N + col] = o1;
        }
    }
}

// ---------------- Flash attention, fp16 mma (no shuffles for P) ----------------
#define QHS 72                      // half stride (144 B) -> conflict-free frags
#define AH_Q 0                      // Qh: 128*72 halves
#define AH_K (128*QHS)              // Kh: 64*72
#define AH_V (AH_K + 64*QHS)        // Vt: 64*72 (transposed: [hd][seq])
#define AH_TOT (AH_V + 64*QHS)      // 18432 halves = 36864 B

__global__ __launch_bounds__(256, 2) void attn_kernel(
    const float* __restrict__ Q, const float* __restrict__ Kb,
    const float* __restrict__ Vb, float* __restrict__ O)
{
    extern __shared__ __half ash[];
    __half* Qh = ash + AH_Q;
    __half* Kh = ash + AH_K;
    __half* Vt = ash + AH_V;

    const int tid  = threadIdx.x;
    const int warp = tid >> 5;
    const int lane = tid & 31;
    const int g    = lane >> 2;
    const int t4   = lane & 3;

    const int h = blockIdx.y;
    const int b = blockIdx.z;
    const size_t base = ((size_t)b * SEQ) * DMODEL + (size_t)h * HD;
    const float scale = 0.125f;
    const int w16 = warp * 16;

    for (int half_i = 0; half_i < 2; half_i++) {
        const int qtile = half_i ? (int)blockIdx.x : (NQT - 1 - (int)blockIdx.x);
        const int q0 = qtile * 128;

        __syncthreads();   // previous half's readers of Qh done

        // Q tile (128x64) -> half, pre-scaled
#pragma unroll
        for (int l = 0; l < 8; l++) {
            int idx = tid + l * 256;
            int row = idx >> 4;
            int col = (idx & 15) * 4;
            float4 v = *(const float4*)&Q[base + (size_t)(q0 + row) * DMODEL + col];
            uint2 u;
            u.x = pack_h2(v.x * scale, v.y * scale);
            u.y = pack_h2(v.z * scale, v.w * scale);
            *(uint2*)&Qh[row * QHS + col] = u;
        }

        float of[8][4];
#pragma unroll
        for (int j = 0; j < 8; j++)
#pragma unroll
            for (int r = 0; r < 4; r++) of[j][r] = 0.f;
        float m0r = -1e30f, m1r = -1e30f, l0r = 0.f, l1r = 0.f;

        const int ntiles = 2 * qtile + 2;

        for (int jt = 0; jt < ntiles; jt++) {
            __syncthreads();
            // K (64x64 -> half rows), V (transposed: Vt[hd][seq])
#pragma unroll
            for (int l = 0; l < 4; l++) {
                int idx = tid + l * 256;
                int row = idx >> 4;
                int col = (idx & 15) * 4;
                size_t gaddr = base + (size_t)(jt * 64 + row) * DMODEL + col;

                float4 kv = *(const float4*)&Kb[gaddr];
                uint2 u;
                u.x = pack_h2(kv.x, kv.y);
                u.y = pack_h2(kv.z, kv.w);
                *(uint2*)&Kh[row * QHS + col] = u;

                float4 vv = *(const float4*)&Vb[gaddr];
                Vt[(col + 0) * QHS + row] = __float2half_rn(vv.x);
                Vt[(col + 1) * QHS + row] = __float2half_rn(vv.y);
                Vt[(col + 2) * QHS + row] = __float2half_rn(vv.z);
                Vt[(col + 3) * QHS + row] = __float2half_rn(vv.w);
            }
            __syncthreads();

            // ---- S = Q @ K^T (4 K=16 steps over hd=64) ----
            float s[8][4];
#pragma unroll
            for (int j = 0; j < 8; j++)
#pragma unroll
                for (int r = 0; r < 4; r++) s[j][r] = 0.f;

#pragma unroll
            for (int ks = 0; ks < 4; ks++) {
                const int k0 = ks * 16;
                u32 aq[4];
                aq[0] = ldh2(&Qh[(w16 + g)     * QHS + k0 + 2 * t4]);
                aq[1] = ldh2(&Qh[(w16 + g + 8) * QHS + k0 + 2 * t4]);
                aq[2] = ldh2(&Qh[(w16 + g)     * QHS + k0 + 2 * t4 + 8]);
                aq[3] = ldh2(&Qh[(w16 + g + 8) * QHS + k0 + 2 * t4 + 8]);
#pragma unroll
                for (int j = 0; j < 8; j++) {
                    u32 bfr[2];
                    bfr[0] = ldh2(&Kh[(j * 8 + g) * QHS + k0 + 2 * t4]);
                    bfr[1] = ldh2(&Kh[(j * 8 + g) * QHS + k0 + 2 * t4 + 8]);
                    mma_f16(s[j], aq, bfr);
                }
            }

            // ---- causal mask (diagonal tiles only) ----
            if (jt >= 2 * qtile) {
                int r0 = q0 + w16 + g, r1 = r0 + 8;
#pragma unroll
                for (int j = 0; j < 8; j++) {
                    int c = jt * 64 + j * 8 + 2 * t4;
                    if (c     > r0) s[j][0] = -1e30f;
                    if (c + 1 > r0) s[j][1] = -1e30f;
                    if (c     > r1) s[j][2] = -1e30f;
                    if (c + 1 > r1) s[j][3] = -1e30f;
                }
            }

            // ---- online softmax ----
            float mt0 = -1e30f, mt1 = -1e30f;
#pragma unroll
            for (int j = 0; j < 8; j++) {
                mt0 = fmaxf(mt0, fmaxf(s[j][0], s[j][1]));
                mt1 = fmaxf(mt1, fmaxf(s[j][2], s[j][3]));
            }
            mt0 = fmaxf(mt0, __shfl_xor_sync(0xffffffffu, mt0, 1));
            mt0 = fmaxf(mt0, __shfl_xor_sync(0xffffffffu, mt0, 2));
            mt1 = fmaxf(mt1, __shfl_xor_sync(0xffffffffu, mt1, 1));
            mt1 = fmaxf(mt1, __shfl_xor_sync(0xffffffffu, mt1, 2));

            float mn0 = fmaxf(m0r, mt0), mn1 = fmaxf(m1r, mt1);
            float corr0 = __expf(m0r - mn0), corr1 = __expf(m1r - mn1);
            m0r = mn0; m1r = mn1;

            float ps0 = 0.f, ps1 = 0.f;
#pragma unroll
            for (int j = 0; j < 8; j++) {
                s[j][0] = __expf(s[j][0] - mn0); ps0 += s[j][0];
                s[j][1] = __expf(s[j][1] - mn0); ps0 += s[j][1];
                s[j][2] = __expf(s[j][2] - mn1); ps1 += s[j][2];
                s[j][3] = __expf(s[j][3] - mn1); ps1 += s[j][3];
            }
            ps0 += __shfl_xor_sync(0xffffffffu, ps0, 1);
            ps0 += __shfl_xor_sync(0xffffffffu, ps0, 2);
            ps1 += __shfl_xor_sync(0xffffffffu, ps1, 1);
            ps1 += __shfl_xor_sync(0xffffffffu, ps1, 2);
            l0r = l0r * corr0 + ps0;
            l1r = l1r * corr1 + ps1;

#pragma unroll
            for (int j = 0; j < 8; j++) {
                of[j][0] *= corr0; of[j][1] *= corr0;
                of[j][2] *= corr1; of[j][3] *= corr1;
            }

            // ---- O += P @ V ----
            // A-fragment of m16n8k16 == packed C-fragment pairs: NO shuffles.
#pragma unroll
            for (int ks = 0; ks < 4; ks++) {
                const int k0 = ks * 16;
                u32 pa[4];
                pa[0] = pack_h2(s[2*ks][0],     s[2*ks][1]);
                pa[1] = pack_h2(s[2*ks][2],     s[2*ks][3]);
                pa[2] = pack_h2(s[2*ks+1][0],   s[2*ks+1][1]);
                pa[3] = pack_h2(s[2*ks+1][2],   s[2*ks+1][3]);
#pragma unroll
                for (int j = 0; j < 8; j++) {
                    u32 vf[2];
                    vf[0] = ldh2(&Vt[(j * 8 + g) * QHS + k0 + 2 * t4]);
                    vf[1] = ldh2(&Vt[(j * 8 + g) * QHS + k0 + 2 * t4 + 8]);
                    mma_f16(of[j], pa, vf);
                }
            }
        }

        // ---- epilogue ----
        float inv0 = 1.f / l0r, inv1 = 1.f / l1r;
        int r0 = q0 + w16 + g, r1 = r0 + 8;
#pragma unroll
        for (int j = 0; j < 8; j++) {
            int col = j * 8 + 2 * t4;
            float2 o0 = { of[j][0] * inv0, of[j][1] * inv0 };
            float2 o1 = { of[j][2] * inv1, of[j][3] * inv1 };
            *(float2*)&O[base + (size_t)r0 * DMODEL + col] = o0;
            *(float2*)&O[base + (size_t)r1 * DMODEL + col] = o1;
        }
    }
}

// ---------------- launch ----------------
extern "C" void kernel_launch(void* const* d_in, const int* in_sizes, int n_in,
                              void* d_out, int out_size)
{
    const float* x  = (const float*)d_in[0];
    const float* wq = (const float*)d_in[1];
    const float* bq = (const float*)d_in[2];
    const float* wk = (const float*)d_in[3];
    const float* bk = (const float*)d_in[4];
    const float* wv = (const float*)d_in[5];
    const float* bv = (const float*)d_in[6];
    const float* wo = (const float*)d_in[7];
    const float* bo = (const float*)d_in[8];
    float* out = (float*)d_out;

    float *qb, *kb, *vb, *ab;
    cudaGetSymbolAddress((void**)&qb, g_q);
    cudaGetSymbolAddress((void**)&kb, g_k);
    cudaGetSymbolAddress((void**)&vb, g_v);
    cudaGetSymbolAddress((void**)&ab, g_attn);

    const int smem_gemm = 2 * (AHSTG + WHSTG) * (int)sizeof(__half);   // 61440 B
    cudaFuncSetAttribute(gemm_h, cudaFuncAttributeMaxDynamicSharedMemorySize, smem_gemm);

    dim3 gdim(DMODEL / GBN, MTOT / GBM);   // (4, 32) = 128 blocks
    gemm_h<<<gdim, 256, smem_gemm>>>(x, wq, bq, qb, MTOT, DMODEL, DMODEL);
    gemm_h<<<gdim, 256, smem_gemm>>>(x, wk, bk, kb, MTOT, DMODEL, DMODEL);
    gemm_h<<<gdim, 256, smem_gemm>>>(x, wv, bv, vb, MTOT, DMODEL, DMODEL);

    const int smem_attn = AH_TOT * (int)sizeof(__half);   // 36864 B
    cudaFuncSetAttribute(attn_kernel, cudaFuncAttributeMaxDynamicSharedMemorySize, smem_attn);
    attn_kernel<<<dim3(NQT / 2, NHEAD, BATCH), 256, smem_attn>>>(qb, kb, vb, ab);

    gemm_h<<<gdim, 256, smem_gemm>>>(ab, wo, bo, out, MTOT, DMODEL, DMODEL);
}

// round 16
// speedup vs baseline: 1.8638x; 1.0016x over previous
#include <cuda_runtime.h>
#include <cuda_fp16.h>
#include <math.h>

typedef unsigned int u32;

// Problem constants
#define BATCH 2
#define SEQ   2048
#define DMODEL 1024
#define NHEAD 16
#define HD    64
#define MTOT  (BATCH*SEQ)
#define NQT   (SEQ/128)

// ---------------- scratch ----------------
__device__ float g_q[BATCH*SEQ*DMODEL];
__device__ float g_k[BATCH*SEQ*DMODEL];
__device__ float g_v[BATCH*SEQ*DMODEL];
__device__ float g_attn[BATCH*SEQ*DMODEL];

// ---------------- helpers ----------------
__device__ __forceinline__ u32 pack_h2(float a, float b) {
    __half2 h = __floats2half2_rn(a, b);   // lo = a, hi = b
    return *(u32*)&h;
}
__device__ __forceinline__ void mma_f16(float* d, const u32* a, const u32* b) {
    asm volatile(
        "mma.sync.aligned.m16n8k16.row.col.f32.f16.f16.f32 "
        "{%0,%1,%2,%3},{%4,%5,%6,%7},{%8,%9},{%0,%1,%2,%3};"
        : "+f"(d[0]), "+f"(d[1]), "+f"(d[2]), "+f"(d[3])
        : "r"(a[0]), "r"(a[1]), "r"(a[2]), "r"(a[3]), "r"(b[0]), "r"(b[1]));
}
__device__ __forceinline__ u32 ldh2(const __half* p) {
    return *(const u32*)p;
}
__device__ __forceinline__ void cpa16(u32 dst, const void* src) {
    asm volatile("cp.async.cg.shared.global [%0], [%1], 16;" :: "r"(dst), "l"(src));
}
#define CP_COMMIT() asm volatile("cp.async.commit_group;")
#define CP_WAIT1()  asm volatile("cp.async.wait_group 1;")
#define CP_WAIT0()  asm volatile("cp.async.wait_group 0;")

// ---------------- GEMM: fp16 mma, 128x256 tile, 64x64 warp tile (round-15, unchanged) ----------------
#define GBM 128
#define GBN 256
#define GBK 32
#define AHS 40
#define AHSTG (GBM*AHS)
#define WHSTG (GBN*AHS)

__global__ __launch_bounds__(256, 1) void gemm_h(
    const float* __restrict__ A, const float* __restrict__ W,
    const float* __restrict__ bias, float* __restrict__ C,
    int M, int N, int K)
{
    extern __shared__ __half hsm[];
    __half* Ah = hsm;
    __half* Wh = hsm + 2 * AHSTG;

    const int tid  = threadIdx.x;
    const int warp = tid >> 5;
    const int lane = tid & 31;
    const int g    = lane >> 2;
    const int t4   = lane & 3;
    const int wm   = warp >> 2;
    const int wn   = warp & 3;
    const int m0   = blockIdx.y * GBM;
    const int n0   = blockIdx.x * GBN;

    float acc[4][8][4];
#pragma unroll
    for (int i = 0; i < 4; i++)
#pragma unroll
        for (int j = 0; j < 8; j++)
#pragma unroll
            for (int r = 0; r < 4; r++) acc[i][j][r] = 0.f;

    float4 ar[4], wr4[8];
    const int skq = (tid & 7) * 4;
    int srA[4], srW[8];
#pragma unroll
    for (int l = 0; l < 4; l++) srA[l] = (tid + 256 * l) >> 3;
#pragma unroll
    for (int l = 0; l < 8; l++) srW[l] = (tid + 256 * l) >> 3;

#pragma unroll
    for (int l = 0; l < 4; l++)
        ar[l] = *(const float4*)&A[(size_t)(m0 + srA[l]) * K + skq];
#pragma unroll
    for (int l = 0; l < 8; l++)
        wr4[l] = *(const float4*)&W[(size_t)(n0 + srW[l]) * K + skq];

    const int NKB = K / GBK;
    for (int kb = 0; kb < NKB; kb++) {
        const int buf = kb & 1;
        __half* Ab = Ah + buf * AHSTG;
        __half* Wb = Wh + buf * WHSTG;

#pragma unroll
        for (int l = 0; l < 4; l++) {
            uint2 u;
            u.x = pack_h2(ar[l].x, ar[l].y);
            u.y = pack_h2(ar[l].z, ar[l].w);
            *(uint2*)&Ab[srA[l] * AHS + skq] = u;
        }
#pragma unroll
        for (int l = 0; l < 8; l++) {
            uint2 u;
            u.x = pack_h2(wr4[l].x, wr4[l].y);
            u.y = pack_h2(wr4[l].z, wr4[l].w);
            *(uint2*)&Wb[srW[l] * AHS + skq] = u;
        }

        if (kb + 1 < NKB) {
            int k0 = (kb + 1) * GBK;
#pragma unroll
            for (int l = 0; l < 4; l++)
                ar[l] = *(const float4*)&A[(size_t)(m0 + srA[l]) * K + k0 + skq];
#pragma unroll
            for (int l = 0; l < 8; l++)
                wr4[l] = *(const float4*)&W[(size_t)(n0 + srW[l]) * K + k0 + skq];
        }

        __syncthreads();

#pragma unroll
        for (int ks = 0; ks < 2; ks++) {
            const int k0 = ks * 16;
            u32 af[4][4];
#pragma unroll
            for (int i = 0; i < 4; i++) {
                int rb = wm * 64 + i * 16 + g;
                af[i][0] = ldh2(&Ab[(rb)     * AHS + k0 + 2 * t4]);
                af[i][1] = ldh2(&Ab[(rb + 8) * AHS + k0 + 2 * t4]);
                af[i][2] = ldh2(&Ab[(rb)     * AHS + k0 + 2 * t4 + 8]);
                af[i][3] = ldh2(&Ab[(rb + 8) * AHS + k0 + 2 * t4 + 8]);
            }
#pragma unroll
            for (int j = 0; j < 8; j++) {
                int nb = wn * 64 + j * 8 + g;
                u32 bf[2];
                bf[0] = ldh2(&Wb[nb * AHS + k0 + 2 * t4]);
                bf[1] = ldh2(&Wb[nb * AHS + k0 + 2 * t4 + 8]);
#pragma unroll
                for (int i = 0; i < 4; i++)
                    mma_f16(acc[i][j], af[i], bf);
            }
        }
        __syncthreads();
    }

#pragma unroll
    for (int j = 0; j < 8; j++) {
        int col = n0 + wn * 64 + j * 8 + 2 * t4;
        float b0 = bias[col], b1 = bias[col + 1];
#pragma unroll
        for (int i = 0; i < 4; i++) {
            int r0 = m0 + wm * 64 + i * 16 + g;
            float2 o0 = { acc[i][j][0] + b0, acc[i][j][1] + b1 };
            float2 o1 = { acc[i][j][2] + b0, acc[i][j][3] + b1 };
            *(float2*)&C[(size_t)r0 * N + col]       = o0;
            *(float2*)&C[(size_t)(r0 + 8) * N + col] = o1;
        }
    }
}

// ---------------- Flash attention, fp16 mma + cp.async double-buffered K/V ----------------
#define QHS 72
#define AH_Q 0
#define AH_K (128*QHS)
#define AH_V (AH_K + 64*QHS)
#define AH_TOT (AH_V + 64*QHS)          // 18432 halves = 36864 B
#define STG_F (AH_TOT * 2)              // byte offset of staging area
#define STG_BUF 8192                    // floats per staging buffer (K 4096 + V 4096)
#define SM_ATTN (STG_F + 2 * STG_BUF * 4)   // 36864 + 65536 = 102400 B

__global__ __launch_bounds__(256, 2) void attn_kernel(
    const float* __restrict__ Q, const float* __restrict__ Kb,
    const float* __restrict__ Vb, float* __restrict__ O)
{
    extern __shared__ char smraw[];
    __half* Qh = (__half*)smraw + AH_Q;
    __half* Kh = (__half*)smraw + AH_K;
    __half* Vt = (__half*)smraw + AH_V;
    float*  Stg = (float*)(smraw + STG_F);
    const u32 stg_base = (u32)__cvta_generic_to_shared(Stg);

    const int tid  = threadIdx.x;
    const int warp = tid >> 5;
    const int lane = tid & 31;
    const int g    = lane >> 2;
    const int t4   = lane & 3;

    const int h = blockIdx.y;
    const int b = blockIdx.z;
    const size_t base = ((size_t)b * SEQ) * DMODEL + (size_t)h * HD;
    const float scale = 0.125f;
    const int w16 = warp * 16;

    // issue K+V tile jt into staging buffer buf (8 cp.async.16B + commit)
    auto issue_tile = [&](int jt, int buf) {
#pragma unroll
        for (int l = 0; l < 4; l++) {
            int idx = tid + l * 256;
            int row = idx >> 4;
            int c4  = (idx & 15) * 4;
            size_t go = base + (size_t)(jt * 64 + row) * DMODEL + c4;
            u32 so = (u32)((buf * STG_BUF + row * 64 + c4) * 4);
            cpa16(stg_base + so, &Kb[go]);
            cpa16(stg_base + so + STG_BUF/2 * 4, &Vb[go]);
        }
        CP_COMMIT();
    };

    for (int half_i = 0; half_i < 2; half_i++) {
        const int qtile = half_i ? (int)blockIdx.x : (NQT - 1 - (int)blockIdx.x);
        const int q0 = qtile * 128;

        __syncthreads();   // previous half's readers of Qh done

        // Q tile (128x64) -> half, pre-scaled
#pragma unroll
        for (int l = 0; l < 8; l++) {
            int idx = tid + l * 256;
            int row = idx >> 4;
            int col = (idx & 15) * 4;
            float4 v = *(const float4*)&Q[base + (size_t)(q0 + row) * DMODEL + col];
            uint2 u;
            u.x = pack_h2(v.x * scale, v.y * scale);
            u.y = pack_h2(v.z * scale, v.w * scale);
            *(uint2*)&Qh[row * QHS + col] = u;
        }

        float of[8][4];
#pragma unroll
        for (int j = 0; j < 8; j++)
#pragma unroll
            for (int r = 0; r < 4; r++) of[j][r] = 0.f;
        float m0r = -1e30f, m1r = -1e30f, l0r = 0.f, l1r = 0.f;

        const int ntiles = 2 * qtile + 2;

        issue_tile(0, 0);   // prologue fetch

        for (int jt = 0; jt < ntiles; jt++) {
            const int buf = jt & 1;
            if (jt + 1 < ntiles) { issue_tile(jt + 1, buf ^ 1); CP_WAIT1(); }
            else                 { CP_WAIT0(); }
            __syncthreads();   // staging[buf] visible to all; prev compute done

            // convert staging[buf] -> Kh (rows) / Vt (transposed), same method as r15
            const float* Ks = Stg + buf * STG_BUF;
            const float* Vs = Ks + STG_BUF/2;
#pragma unroll
            for (int l = 0; l < 4; l++) {
                int idx = tid + l * 256;
                int row = idx >> 4;
                int col = (idx & 15) * 4;
                float4 kv = *(const float4*)&Ks[row * 64 + col];
                uint2 u;
                u.x = pack_h2(kv.x, kv.y);
                u.y = pack_h2(kv.z, kv.w);
                *(uint2*)&Kh[row * QHS + col] = u;

                float4 vv = *(const float4*)&Vs[row * 64 + col];
                Vt[(col + 0) * QHS + row] = __float2half_rn(vv.x);
                Vt[(col + 1) * QHS + row] = __float2half_rn(vv.y);
                Vt[(col + 2) * QHS + row] = __float2half_rn(vv.z);
                Vt[(col + 3) * QHS + row] = __float2half_rn(vv.w);
            }
            __syncthreads();

            // ---- S = Q @ K^T ----
            float s[8][4];
#pragma unroll
            for (int j = 0; j < 8; j++)
#pragma unroll
                for (int r = 0; r < 4; r++) s[j][r] = 0.f;

#pragma unroll
            for (int ks = 0; ks < 4; ks++) {
                const int k0 = ks * 16;
                u32 aq[4];
                aq[0] = ldh2(&Qh[(w16 + g)     * QHS + k0 + 2 * t4]);
                aq[1] = ldh2(&Qh[(w16 + g + 8) * QHS + k0 + 2 * t4]);
                aq[2] = ldh2(&Qh[(w16 + g)     * QHS + k0 + 2 * t4 + 8]);
                aq[3] = ldh2(&Qh[(w16 + g + 8) * QHS + k0 + 2 * t4 + 8]);
#pragma unroll
                for (int j = 0; j < 8; j++) {
                    u32 bfr[2];
                    bfr[0] = ldh2(&Kh[(j * 8 + g) * QHS + k0 + 2 * t4]);
                    bfr[1] = ldh2(&Kh[(j * 8 + g) * QHS + k0 + 2 * t4 + 8]);
                    mma_f16(s[j], aq, bfr);
                }
            }

            // ---- causal mask (diagonal tiles only) ----
            if (jt >= 2 * qtile) {
                int r0 = q0 + w16 + g, r1 = r0 + 8;
#pragma unroll
                for (int j = 0; j < 8; j++) {
                    int c = jt * 64 + j * 8 + 2 * t4;
                    if (c     > r0) s[j][0] = -1e30f;
                    if (c + 1 > r0) s[j][1] = -1e30f;
                    if (c     > r1) s[j][2] = -1e30f;
                    if (c + 1 > r1) s[j][3] = -1e30f;
                }
            }

            // ---- online softmax ----
            float mt0 = -1e30f, mt1 = -1e30f;
#pragma unroll
            for (int j = 0; j < 8; j++) {
                mt0 = fmaxf(mt0, fmaxf(s[j][0], s[j][1]));
                mt1 = fmaxf(mt1, fmaxf(s[j][2], s[j][3]));
            }
            mt0 = fmaxf(mt0, __shfl_xor_sync(0xffffffffu, mt0, 1));
            mt0 = fmaxf(mt0, __shfl_xor_sync(0xffffffffu, mt0, 2));
            mt1 = fmaxf(mt1, __shfl_xor_sync(0xffffffffu, mt1, 1));
            mt1 = fmaxf(mt1, __shfl_xor_sync(0xffffffffu, mt1, 2));

            float mn0 = fmaxf(m0r, mt0), mn1 = fmaxf(m1r, mt1);
            float corr0 = __expf(m0r - mn0), corr1 = __expf(m1r - mn1);
            m0r = mn0; m1r = mn1;

            float ps0 = 0.f, ps1 = 0.f;
#pragma unroll
            for (int j = 0; j < 8; j++) {
                s[j][0] = __expf(s[j][0] - mn0); ps0 += s[j][0];
                s[j][1] = __expf(s[j][1] - mn0); ps0 += s[j][1];
                s[j][2] = __expf(s[j][2] - mn1); ps1 += s[j][2];
                s[j][3] = __expf(s[j][3] - mn1); ps1 += s[j][3];
            }
            ps0 += __shfl_xor_sync(0xffffffffu, ps0, 1);
            ps0 += __shfl_xor_sync(0xffffffffu, ps0, 2);
            ps1 += __shfl_xor_sync(0xffffffffu, ps1, 1);
            ps1 += __shfl_xor_sync(0xffffffffu, ps1, 2);
            l0r = l0r * corr0 + ps0;
            l1r = l1r * corr1 + ps1;

#pragma unroll
            for (int j = 0; j < 8; j++) {
                of[j][0] *= corr0; of[j][1] *= corr0;
                of[j][2] *= corr1; of[j][3] *= corr1;
            }

            // ---- O += P @ V (A-fragment packed straight from C-fragments) ----
#pragma unroll
            for (int ks = 0; ks < 4; ks++) {
                const int k0 = ks * 16;
                u32 pa[4];
                pa[0] = pack_h2(s[2*ks][0],   s[2*ks][1]);
                pa[1] = pack_h2(s[2*ks][2],   s[2*ks][3]);
                pa[2] = pack_h2(s[2*ks+1][0], s[2*ks+1][1]);
                pa[3] = pack_h2(s[2*ks+1][2], s[2*ks+1][3]);
#pragma unroll
                for (int j = 0; j < 8; j++) {
                    u32 vf[2];
                    vf[0] = ldh2(&Vt[(j * 8 + g) * QHS + k0 + 2 * t4]);
                    vf[1] = ldh2(&Vt[(j * 8 + g) * QHS + k0 + 2 * t4 + 8]);
                    mma_f16(of[j], pa, vf);
                }
            }
        }

        // ---- epilogue ----
        float inv0 = 1.f / l0r, inv1 = 1.f / l1r;
        int r0 = q0 + w16 + g, r1 = r0 + 8;
#pragma unroll
        for (int j = 0; j < 8; j++) {
            int col = j * 8 + 2 * t4;
            float2 o0 = { of[j][0] * inv0, of[j][1] * inv0 };
            float2 o1 = { of[j][2] * inv1, of[j][3] * inv1 };
            *(float2*)&O[base + (size_t)r0 * DMODEL + col] = o0;
            *(float2*)&O[base + (size_t)r1 * DMODEL + col] = o1;
        }
    }
}

// ---------------- launch ----------------
extern "C" void kernel_launch(void* const* d_in, const int* in_sizes, int n_in,
                              void* d_out, int out_size)
{
    const float* x  = (const float*)d_in[0];
    const float* wq = (const float*)d_in[1];
    const float* bq = (const float*)d_in[2];
    const float* wk = (const float*)d_in[3];
    const float* bk = (const float*)d_in[4];
    const float* wv = (const float*)d_in[5];
    const float* bv = (const float*)d_in[6];
    const float* wo = (const float*)d_in[7];
    const float* bo = (const float*)d_in[8];
    float* out = (float*)d_out;

    float *qb, *kb, *vb, *ab;
    cudaGetSymbolAddress((void**)&qb, g_q);
    cudaGetSymbolAddress((void**)&kb, g_k);
    cudaGetSymbolAddress((void**)&vb, g_v);
    cudaGetSymbolAddress((void**)&ab, g_attn);

    const int smem_gemm = 2 * (AHSTG + WHSTG) * (int)sizeof(__half);   // 61440 B
    cudaFuncSetAttribute(gemm_h, cudaFuncAttributeMaxDynamicSharedMemorySize, smem_gemm);

    dim3 gdim(DMODEL / GBN, MTOT / GBM);   // (4, 32) = 128 blocks
    gemm_h<<<gdim, 256, smem_gemm>>>(x, wq, bq, qb, MTOT, DMODEL, DMODEL);
    gemm_h<<<gdim, 256, smem_gemm>>>(x, wk, bk, kb, MTOT, DMODEL, DMODEL);
    gemm_h<<<gdim, 256, smem_gemm>>>(x, wv, bv, vb, MTOT, DMODEL, DMODEL);

    cudaFuncSetAttribute(attn_kernel, cudaFuncAttributeMaxDynamicSharedMemorySize, SM_ATTN);
    attn_kernel<<<dim3(NQT / 2, NHEAD, BATCH), 256, SM_ATTN>>>(qb, kb, vb, ab);

    gemm_h<<<gdim, 256, smem_gemm>>>(ab, wo, bo, out, MTOT, DMODEL, DMODEL);
}